// round 10
// baseline (speedup 1.0000x reference)
#include <cuda_runtime.h>
#include <cmath>
#include <cstdint>

#define D_MODEL 512
#define SEQ     1024
#define NB      8
#define NHEADS  8
#define DHEAD   64
#define FF      2048
#define NROWS   (NB*SEQ)    /* 8192 */
#define NDEPTH  3

// ---------------- scratch (device globals; no allocation allowed) ----------
__device__ float g_x   [NROWS * D_MODEL];
__device__ float g_h   [NROWS * D_MODEL];          // split-bf16 layout
__device__ float g_qkv [NROWS * 3 * D_MODEL];
__device__ float g_sim [67108864];                 // fp32 then split-bf16 in place
__device__ float g_ao  [NROWS * D_MODEL];          // split-bf16 layout
__device__ float g_ffg [NROWS * FF];
__device__ float g_pool[NB * 8 * D_MODEL];
__device__ float g_wt  [12845056];                 // transposed weights (fp32)
__device__ float g_ws  [12845056];                 // split bf16 hi/lo weight planes
__device__ float g_vt  [NB * NHEADS * DHEAD * SEQ];// V^T per (b,h): [64][1024]

#define OFF_PROJ 0
#define OFF_QKV  262144
#define OFF_WOUT 2621440
#define OFF_W1   3407872
#define OFF_W2   9699328

// GEMM modes
#define M_PLAIN 0
#define M_GEGLU 1

// ---------------------------------------------------------------------------
__device__ __forceinline__ void cp16(uint32_t sa, const float* ga) {
    asm volatile("cp.async.cg.shared.global [%0], [%1], 16;" :: "r"(sa), "l"(ga) : "memory");
}
__device__ __forceinline__ uint32_t smem_u32(const void* p) {
    uint32_t a;
    asm("{ .reg .u64 t; cvta.to.shared.u64 t, %1; cvt.u32.u64 %0, t; }"
        : "=r"(a) : "l"(p));
    return a;
}
__device__ __forceinline__ void cp_commit() {
    asm volatile("cp.async.commit_group;" ::: "memory");
}
// bf16x3 MMA: m16n8k16, row.col, f32 accum
__device__ __forceinline__ void mma16(float* d, const uint32_t* a, const uint32_t* b) {
    asm volatile(
        "mma.sync.aligned.m16n8k16.row.col.f32.bf16.bf16.f32 "
        "{%0,%1,%2,%3}, {%4,%5,%6,%7}, {%8,%9}, {%0,%1,%2,%3};"
        : "+f"(d[0]), "+f"(d[1]), "+f"(d[2]), "+f"(d[3])
        : "r"(a[0]), "r"(a[1]), "r"(a[2]), "r"(a[3]), "r"(b[0]), "r"(b[1]));
}
// split float2 -> packed bf16 hi pair + packed bf16 lo pair
__device__ __forceinline__ void split2(float2 v, uint32_t& hi, uint32_t& lo) {
    asm("cvt.rn.bf16x2.f32 %0, %1, %2;" : "=r"(hi) : "f"(v.y), "f"(v.x));
    const float h0 = __uint_as_float(hi << 16);
    const float h1 = __uint_as_float(hi & 0xFFFF0000u);
    const float r0 = v.x - h0;
    const float r1 = v.y - h1;
    asm("cvt.rn.bf16x2.f32 %0, %1, %2;" : "=r"(lo) : "f"(r1), "f"(r0));
}

// ---------------------------------------------------------------------------
// bf16x3 mma.sync GEMM:  C[M,N] = alpha * A[M,K] @ Bt[N,K]^T (+bias+resid+pos)
// Split layout (per row, per 32-k chunk = 128B): 16 words of packed (k,k+1)
// bf16 hi pairs, then 16 words of lo pairs. Same bytes/row as fp32, so the
// stage loader never changes; only the fragment path does.
//   BSPLIT: B operand is pre-split.   ASPLIT: A operand is pre-split.
//   OSPLIT: epilogue emits C in split layout (PLAIN only, no bias/resid/pos).
// MODE == M_GEGLU: B cols interleaved (a0,g0,...); epilogue stores
//   (a+b_a)*gelu(g+b_g) at C[row, col/2], ldc = FF.
// ---------------------------------------------------------------------------
template<int BN, int MODE, bool BSPLIT, bool ASPLIT, bool OSPLIT>
__global__ void __launch_bounds__(256, 2)
mgemm_kernel(const float* __restrict__ A, long lda, long aO, long aI,
             const float* __restrict__ B, long ldb, long bO, long bI,
             float* __restrict__ C, long ldc, long cO, long cI,
             int K,
             const float* __restrict__ bias,
             const float* __restrict__ resid,
             const float* __restrict__ pos,
             float alpha)
{
    constexpr int BM = 128;
    constexpr int WN = BN / 2;       // warp tile: 32 x WN (4x2 warp grid)
    constexpr int NI = WN / 8;       // n-tiles per warp
    constexpr int PITCH = 40;        // floats per smem row (160B)
    constexpr int STAGE_F = (BM + BN) * PITCH;

    extern __shared__ float smem[];

    const int z = blockIdx.z, zo = z >> 3, zi = z & 7;
    A += zo * aO + zi * aI;
    B += zo * bO + zi * bI;
    C += zo * cO + zi * cI;
    const float* Rz = resid ? resid + zo * cO + zi * cI : nullptr;

    const long m0 = (long)blockIdx.y * BM;
    const long n0 = (long)blockIdx.x * BN;
    A += m0 * lda;
    B += n0 * ldb;

    const int t    = threadIdx.x;
    const int wid  = t >> 5, lane = t & 31;
    const int wr   = wid & 3, wc = wid >> 2;
    const int g    = lane >> 2, c = lane & 3;

    const uint32_t sbase = smem_u32(smem);
    const int niter = K >> 5;        // chunks of K=32

    auto load_stage = [&](int s, int kc) {
        const uint32_t sA = sbase + (uint32_t)(s * STAGE_F) * 4u;
        const uint32_t sB = sA + BM * PITCH * 4u;
        const float* ga = A + kc * 32;
        const float* gb = B + kc * 32;   // 128B per 32-k chunk in both layouts
        const int r0  = t >> 3;
        const int seg = (t & 7) * 16;
#pragma unroll
        for (int p = 0; p < BM / 32; ++p) {
            const int r = p * 32 + r0;
            cp16(sA + r * 160 + seg, ga + (long)r * lda + (t & 7) * 4);
        }
#pragma unroll
        for (int p = 0; p < BN / 32; ++p) {
            const int r = p * 32 + r0;
            cp16(sB + r * 160 + seg, gb + (long)r * ldb + (t & 7) * 4);
        }
        cp_commit();
    };

    float acc[2][NI][4];
#pragma unroll
    for (int mi = 0; mi < 2; ++mi)
#pragma unroll
        for (int ni = 0; ni < NI; ++ni)
#pragma unroll
            for (int j = 0; j < 4; ++j) acc[mi][ni][j] = 0.f;

    load_stage(0, 0);

    for (int i = 0; i < niter; ++i) {
        if (i + 1 < niter) {
            load_stage((i + 1) & 1, i + 1);
            asm volatile("cp.async.wait_group 1;" ::: "memory");
        } else {
            asm volatile("cp.async.wait_group 0;" ::: "memory");
        }
        __syncthreads();

        const float* As = smem + (i & 1) * STAGE_F;
        const float* Bs = As + BM * PITCH;
        const uint32_t* Au = (const uint32_t*)As;
        const uint32_t* Bu = (const uint32_t*)Bs;

#pragma unroll
        for (int ks = 0; ks < 2; ++ks) {      // two k16 steps per K=32 chunk
            const int kk = ks * 16 + 2 * c;
            uint32_t ah[2][4], al[2][4];
#pragma unroll
            for (int mi = 0; mi < 2; ++mi) {
                if (ASPLIT) {
                    const int rb2 = (wr * 32 + mi * 16 + g) * PITCH + ks * 8 + c;
                    ah[mi][0] = Au[rb2];
                    ah[mi][1] = Au[rb2 + 8 * PITCH];
                    ah[mi][2] = Au[rb2 + 4];
                    ah[mi][3] = Au[rb2 + 8 * PITCH + 4];
                    al[mi][0] = Au[rb2 + 16];
                    al[mi][1] = Au[rb2 + 8 * PITCH + 16];
                    al[mi][2] = Au[rb2 + 20];
                    al[mi][3] = Au[rb2 + 8 * PITCH + 20];
                } else {
                    const int rb = (wr * 32 + mi * 16 + g) * PITCH + kk;
                    split2(*(const float2*)&As[rb],                 ah[mi][0], al[mi][0]);
                    split2(*(const float2*)&As[rb + 8 * PITCH],     ah[mi][1], al[mi][1]);
                    split2(*(const float2*)&As[rb + 8],             ah[mi][2], al[mi][2]);
                    split2(*(const float2*)&As[rb + 8 * PITCH + 8], ah[mi][3], al[mi][3]);
                }
            }
            uint32_t bh[NI][2], bl[NI][2];
#pragma unroll
            for (int ni = 0; ni < NI; ++ni) {
                if (BSPLIT) {
                    const int rb2 = (wc * WN + ni * 8 + g) * PITCH + ks * 8 + c;
                    bh[ni][0] = Bu[rb2];
                    bh[ni][1] = Bu[rb2 + 4];
                    bl[ni][0] = Bu[rb2 + 16];
                    bl[ni][1] = Bu[rb2 + 20];
                } else {
                    const int rb = (wc * WN + ni * 8 + g) * PITCH + kk;
                    split2(*(const float2*)&Bs[rb],     bh[ni][0], bl[ni][0]);
                    split2(*(const float2*)&Bs[rb + 8], bh[ni][1], bl[ni][1]);
                }
            }
#pragma unroll
            for (int mi = 0; mi < 2; ++mi)
#pragma unroll
                for (int ni = 0; ni < NI; ++ni) {
                    mma16(acc[mi][ni], al[mi], bh[ni]);
                    mma16(acc[mi][ni], ah[mi], bl[ni]);
                    mma16(acc[mi][ni], ah[mi], bh[ni]);
                }
        }
        __syncthreads();
    }

    // ---- epilogue ----
#pragma unroll
    for (int mi = 0; mi < 2; ++mi) {
#pragma unroll
        for (int ni = 0; ni < NI; ++ni) {
            const long col = n0 + wc * WN + ni * 8 + 2 * c;
#pragma unroll
            for (int h = 0; h < 2; ++h) {
                const long row = m0 + wr * 32 + mi * 16 + g + h * 8;
                float vx = acc[mi][ni][2 * h];
                float vy = acc[mi][ni][2 * h + 1];
                if (MODE == M_GEGLU) {
                    const long j = col >> 1;
                    const float a  = vx + bias[j];
                    const float gg = vy + bias[j + FF];
                    C[row * ldc + j] = a * gg * normcdff(gg);
                } else if (OSPLIT) {
                    // emit split layout: pairs along N (= K of consumer GEMM)
                    uint32_t hi, lo;
                    split2(make_float2(vx * alpha, vy * alpha), hi, lo);
                    const long po = row * ldc + ((col >> 5) << 5) + ((col >> 1) & 15);
                    ((uint32_t*)C)[po]      = hi;
                    ((uint32_t*)C)[po + 16] = lo;
                } else {
                    vx *= alpha; vy *= alpha;
                    if (bias) {
                        float2 bv = *(const float2*)&bias[col];
                        vx += bv.x; vy += bv.y;
                    }
                    const long off = row * ldc + col;
                    if (Rz) {
                        float2 rv = *(const float2*)&Rz[off];
                        vx += rv.x; vy += rv.y;
                    }
                    if (pos) {
                        float2 pv = *(const float2*)&pos[(row & (SEQ - 1)) * D_MODEL + col];
                        vx += pv.x; vy += pv.y;
                    }
                    *(float2*)&C[off] = make_float2(vx, vy);
                }
            }
        }
    }
}

// ---------------------------------------------------------------------------
// Convert fp32 [N,K] row-major -> split bf16 layout.
// ---------------------------------------------------------------------------
__global__ void __launch_bounds__(256)
split_weights_kernel(const float* __restrict__ in, uint32_t* __restrict__ out,
                     int K, long total_pairs)
{
    const long idx = (long)blockIdx.x * 256 + threadIdx.x;
    if (idx >= total_pairs) return;
    const int  kp   = K >> 1;
    const long row  = idx / kp;
    const int  pid  = (int)(idx - row * kp);
    const int  kc   = pid >> 4;
    const int  pl   = pid & 15;
    const int  k0   = kc * 32 + pl * 2;
    float2 v = *(const float2*)&in[row * K + k0];
    uint32_t hi, lo;
    split2(v, hi, lo);
    out[row * K + kc * 32 + pl]      = hi;
    out[row * K + kc * 32 + 16 + pl] = lo;
}

// ---------------------------------------------------------------------------
__global__ void __launch_bounds__(256)
transpose_kernel(const float* __restrict__ in, long ldi, long iO, long iI,
                 float* __restrict__ out, long ldo, long oO, long oI)
{
    __shared__ float tile[32][33];
    const int z = blockIdx.z;
    in  += (z >> 3) * iO + (z & 7) * iI;
    out += (z >> 3) * oO + (z & 7) * oI;
    const long r0 = (long)blockIdx.y * 32, c0 = (long)blockIdx.x * 32;
#pragma unroll
    for (int i = 0; i < 32; i += 8)
        tile[threadIdx.y + i][threadIdx.x] =
            in[(r0 + threadIdx.y + i) * ldi + c0 + threadIdx.x];
    __syncthreads();
#pragma unroll
    for (int i = 0; i < 32; i += 8)
        out[(c0 + threadIdx.y + i) * ldo + r0 + threadIdx.x] =
            tile[threadIdx.x][threadIdx.y + i];
}

// W1 transpose with a/g interleave
__global__ void __launch_bounds__(256)
transpose_w1_kernel(const float* __restrict__ in, float* __restrict__ out)
{
    __shared__ float tile[32][33];
    const int z = blockIdx.z;                   // layer
    in  += (long)z * D_MODEL * (2 * FF);
    out += (long)z * (2 * FF) * D_MODEL;
    const long r0 = (long)blockIdx.y * 32;
    const long c0 = (long)blockIdx.x * 32;
#pragma unroll
    for (int i = 0; i < 32; i += 8)
        tile[threadIdx.y + i][threadIdx.x] =
            in[(r0 + threadIdx.y + i) * (2 * FF) + c0 + threadIdx.x];
    __syncthreads();
#pragma unroll
    for (int i = 0; i < 32; i += 8) {
        const long n = c0 + threadIdx.y + i;
        const long r_out = (n < FF) ? 2 * n : 2 * (n - FF) + 1;
        out[r_out * D_MODEL + r0 + threadIdx.x] = tile[threadIdx.x][threadIdx.y + i];
    }
}

// ---------------------------------------------------------------------------
// LayerNorm; output written in split-bf16 layout (consumed only as GEMM A).
// ---------------------------------------------------------------------------
__global__ void __launch_bounds__(128)
ln_kernel(const float* __restrict__ x, const float* __restrict__ g,
          const float* __restrict__ b, float* __restrict__ o)
{
    __shared__ float sh[4];
    const long row = blockIdx.x;
    const int  t   = threadIdx.x;
    float4 v = ((const float4*)(x + row * D_MODEL))[t];

    float s = v.x + v.y + v.z + v.w;
#pragma unroll
    for (int off = 16; off; off >>= 1) s += __shfl_xor_sync(~0u, s, off);
    if ((t & 31) == 0) sh[t >> 5] = s;
    __syncthreads();
    const float mu = (sh[0] + sh[1] + sh[2] + sh[3]) * (1.f / D_MODEL);

    const float dx = v.x - mu, dy = v.y - mu, dz = v.z - mu, dw = v.w - mu;
    float s2 = dx * dx + dy * dy + dz * dz + dw * dw;
#pragma unroll
    for (int off = 16; off; off >>= 1) s2 += __shfl_xor_sync(~0u, s2, off);
    __syncthreads();
    if ((t & 31) == 0) sh[t >> 5] = s2;
    __syncthreads();
    const float var = (sh[0] + sh[1] + sh[2] + sh[3]) * (1.f / D_MODEL);
    const float r   = rsqrtf(var + 1e-5f);

    float4 gg = ((const float4*)g)[t];
    float4 bb = ((const float4*)b)[t];
    float4 ov;
    ov.x = dx * r * gg.x + bb.x;
    ov.y = dy * r * gg.y + bb.y;
    ov.z = dz * r * gg.z + bb.z;
    ov.w = dw * r * gg.w + bb.w;

    // split-bf16 store: thread t owns pairs 2t, 2t+1 (cols 4t..4t+3)
    uint32_t h0, l0, h1, l1;
    split2(make_float2(ov.x, ov.y), h0, l0);
    split2(make_float2(ov.z, ov.w), h1, l1);
    uint32_t* orow = (uint32_t*)(o + row * D_MODEL);
    const int base = (t >> 3) * 32 + ((2 * t) & 15);
    orow[base]      = h0;
    orow[base + 1]  = h1;
    orow[base + 16] = l0;
    orow[base + 17] = l1;
}

// ---------------------------------------------------------------------------
// Sparsemax, warp-per-row; 15-iter bisection + exact Michelot refinement.
// Output written IN PLACE in split-bf16 layout (consumed only as AV GEMM A).
// ---------------------------------------------------------------------------
__global__ void __launch_bounds__(256)
sparsemax_kernel(float* __restrict__ sim)
{
    const long row  = (long)blockIdx.x * 8 + (threadIdx.x >> 5);
    const int  lane = threadIdx.x & 31;
    float4* base = (float4*)(sim + row * (long)SEQ);

    float4 z[8];
#pragma unroll
    for (int j = 0; j < 8; ++j) z[j] = base[j * 32 + lane];

    float m = -1e30f;
#pragma unroll
    for (int j = 0; j < 8; ++j)
        m = fmaxf(m, fmaxf(fmaxf(z[j].x, z[j].y), fmaxf(z[j].z, z[j].w)));
#pragma unroll
    for (int off = 16; off; off >>= 1) m = fmaxf(m, __shfl_xor_sync(~0u, m, off));

    float lo = m - 1.f, hi = m;
#pragma unroll 1
    for (int it = 0; it < 15; ++it) {
        const float tau = 0.5f * (lo + hi);
        float s = 0.f;
#pragma unroll
        for (int j = 0; j < 8; ++j) {
            s += fmaxf(z[j].x - tau, 0.f) + fmaxf(z[j].y - tau, 0.f)
               + fmaxf(z[j].z - tau, 0.f) + fmaxf(z[j].w - tau, 0.f);
        }
#pragma unroll
        for (int off = 16; off; off >>= 1) s += __shfl_xor_sync(~0u, s, off);
        if (s >= 1.f) lo = tau; else hi = tau;
    }
    {
        const float tau = 0.5f * (lo + hi);
        float s = 0.f, k = 0.f;
#pragma unroll
        for (int j = 0; j < 8; ++j) {
            if (z[j].x > tau) { s += z[j].x; k += 1.f; }
            if (z[j].y > tau) { s += z[j].y; k += 1.f; }
            if (z[j].z > tau) { s += z[j].z; k += 1.f; }
            if (z[j].w > tau) { s += z[j].w; k += 1.f; }
        }
#pragma unroll
        for (int off = 16; off; off >>= 1) {
            s += __shfl_xor_sync(~0u, s, off);
            k += __shfl_xor_sync(~0u, k, off);
        }
        const float tau_x = (s - 1.f) / k;
        uint32_t* orow = (uint32_t*)(sim + row * (long)SEQ);
#pragma unroll
        for (int j = 0; j < 8; ++j) {
            const float ox = fmaxf(z[j].x - tau_x, 0.f);
            const float oy = fmaxf(z[j].y - tau_x, 0.f);
            const float oz = fmaxf(z[j].z - tau_x, 0.f);
            const float ow = fmaxf(z[j].w - tau_x, 0.f);
            uint32_t h0, l0, h1, l1;
            split2(make_float2(ox, oy), h0, l0);
            split2(make_float2(oz, ow), h1, l1);
            const int q = j * 32 + lane;                 // float4 index in row
            const int ob = (q >> 3) * 32 + ((2 * q) & 15);
            orow[ob]      = h0;
            orow[ob + 1]  = h1;
            orow[ob + 16] = l0;
            orow[ob + 17] = l1;
        }
    }
}

// ---------------------------------------------------------------------------
__global__ void __launch_bounds__(512)
pool1_kernel(const float* __restrict__ x, float* __restrict__ p)
{
    const int b = blockIdx.x, cc = blockIdx.y;
    const int d = threadIdx.x;
    float s = 0.f;
    const float* base = x + ((long)b * SEQ + cc * 128) * D_MODEL + d;
    for (int i = 0; i < 128; ++i) s += base[(long)i * D_MODEL];
    p[(b * 8 + cc) * D_MODEL + d] = s;
}

__global__ void __launch_bounds__(256)
pool2_kernel(const float* __restrict__ p, float* __restrict__ o)
{
    const int i = blockIdx.x * blockDim.x + threadIdx.x;
    const int b = i >> 9, d = i & 511;
    float s = 0.f;
#pragma unroll
    for (int cc = 0; cc < 8; ++cc) s += p[(b * 8 + cc) * D_MODEL + d];
    o[i] = s * (1.f / SEQ);
}

// ---------------------------------------------------------------------------
#define SMEM_BN128 (2 * (128 + 128) * 160)
#define SMEM_BN64  (2 * (128 +  64) * 160)

template<int BN, int MODE, bool BSPLIT, bool ASPLIT, bool OSPLIT>
static void launch_mg(const float* A, long lda, long aO, long aI,
                      const float* B, long ldb, long bO, long bI,
                      float* C, long ldc, long cO, long cI,
                      int M, int N, int K, int batches,
                      const float* bias, const float* resid,
                      const float* pos, float alpha)
{
    dim3 grid(N / BN, M / 128, batches);
    const int smem = (BN == 128) ? SMEM_BN128 : SMEM_BN64;
    mgemm_kernel<BN, MODE, BSPLIT, ASPLIT, OSPLIT><<<grid, 256, smem>>>(
        A, lda, aO, aI, B, ldb, bO, bI, C, ldc, cO, cI, K, bias, resid, pos, alpha);
}

extern "C" void kernel_launch(void* const* d_in, const int* in_sizes, int n_in,
                              void* d_out, int out_size)
{
    const float* x      = (const float*)d_in[0];
    const float* proj_w = (const float*)d_in[1];
    const float* proj_b = (const float*)d_in[2];
    const float* pos    = (const float*)d_in[3];
    const float* ln1_g  = (const float*)d_in[4];
    const float* ln1_b  = (const float*)d_in[5];
    const float* wqkv   = (const float*)d_in[6];
    const float* wout   = (const float*)d_in[7];
    const float* bout   = (const float*)d_in[8];
    const float* ln2_g  = (const float*)d_in[9];
    const float* ln2_b  = (const float*)d_in[10];
    const float* w1     = (const float*)d_in[11];
    const float* b1     = (const float*)d_in[12];
    const float* w2     = (const float*)d_in[13];
    const float* b2     = (const float*)d_in[14];
    float* out = (float*)d_out;

    cudaFuncSetAttribute((const void*)mgemm_kernel<128, M_PLAIN, true, false, false>,
                         cudaFuncAttributeMaxDynamicSharedMemorySize, SMEM_BN128);
    cudaFuncSetAttribute((const void*)mgemm_kernel<128, M_PLAIN, true, true, false>,
                         cudaFuncAttributeMaxDynamicSharedMemorySize, SMEM_BN128);
    cudaFuncSetAttribute((const void*)mgemm_kernel<128, M_PLAIN, false, false, false>,
                         cudaFuncAttributeMaxDynamicSharedMemorySize, SMEM_BN128);
    cudaFuncSetAttribute((const void*)mgemm_kernel<128, M_GEGLU, true, true, false>,
                         cudaFuncAttributeMaxDynamicSharedMemorySize, SMEM_BN128);
    cudaFuncSetAttribute((const void*)mgemm_kernel<64, M_PLAIN, false, true, true>,
                         cudaFuncAttributeMaxDynamicSharedMemorySize, SMEM_BN64);

    float *gx, *gh, *gqkv, *gsim, *gao, *gffg, *gpool, *gwt, *gws, *gvt;
    cudaGetSymbolAddress((void**)&gx,    g_x);
    cudaGetSymbolAddress((void**)&gh,    g_h);
    cudaGetSymbolAddress((void**)&gqkv,  g_qkv);
    cudaGetSymbolAddress((void**)&gsim,  g_sim);
    cudaGetSymbolAddress((void**)&gao,   g_ao);
    cudaGetSymbolAddress((void**)&gffg,  g_ffg);
    cudaGetSymbolAddress((void**)&gpool, g_pool);
    cudaGetSymbolAddress((void**)&gwt,   g_wt);
    cudaGetSymbolAddress((void**)&gws,   g_ws);
    cudaGetSymbolAddress((void**)&gvt,   g_vt);

    // ---- weight transposes (B operands as [N,K] row-major, fp32) ----
    transpose_kernel<<<dim3(16, 16, 1), dim3(32, 8)>>>(
        proj_w, D_MODEL, 0, 0, gwt + OFF_PROJ, D_MODEL, 0, 0);
    transpose_kernel<<<dim3(48, 16, 3), dim3(32, 8)>>>(
        wqkv, 3 * D_MODEL, 0, (long)D_MODEL * 3 * D_MODEL,
        gwt + OFF_QKV, D_MODEL, 0, (long)3 * D_MODEL * D_MODEL);
    transpose_kernel<<<dim3(16, 16, 3), dim3(32, 8)>>>(
        wout, D_MODEL, 0, (long)D_MODEL * D_MODEL,
        gwt + OFF_WOUT, D_MODEL, 0, (long)D_MODEL * D_MODEL);
    transpose_w1_kernel<<<dim3(128, 16, 3), dim3(32, 8)>>>(w1, gwt + OFF_W1);
    transpose_kernel<<<dim3(16, 64, 3), dim3(32, 8)>>>(
        w2, D_MODEL, 0, (long)FF * D_MODEL,
        gwt + OFF_W2, FF, 0, (long)D_MODEL * FF);

    // ---- pre-split all weights into bf16 hi/lo planes ----
    {
        long pairs = (long)512 * 256;
        split_weights_kernel<<<(pairs + 255) / 256, 256>>>(
            gwt + OFF_PROJ, (uint32_t*)(gws + OFF_PROJ), 512, pairs);
        pairs = (long)3 * 1536 * 256;
        split_weights_kernel<<<(pairs + 255) / 256, 256>>>(
            gwt + OFF_QKV, (uint32_t*)(gws + OFF_QKV), 512, pairs);
        pairs = (long)3 * 512 * 256;
        split_weights_kernel<<<(pairs + 255) / 256, 256>>>(
            gwt + OFF_WOUT, (uint32_t*)(gws + OFF_WOUT), 512, pairs);
        pairs = (long)3 * 4096 * 256;
        split_weights_kernel<<<(pairs + 255) / 256, 256>>>(
            gwt + OFF_W1, (uint32_t*)(gws + OFF_W1), 512, pairs);
        pairs = (long)3 * 512 * 1024;
        split_weights_kernel<<<(pairs + 255) / 256, 256>>>(
            gwt + OFF_W2, (uint32_t*)(gws + OFF_W2), 2048, pairs);
    }

    // x = x @ proj_w + proj_b + pos
    launch_mg<128, M_PLAIN, true, false, false>(
        x, D_MODEL, 0, 0, gws + OFF_PROJ, D_MODEL, 0, 0,
        gx, D_MODEL, 0, 0, NROWS, D_MODEL, D_MODEL, 1,
        proj_b, nullptr, pos, 1.f);

    const float scale = 0.125f;

    for (int l = 0; l < NDEPTH; ++l) {
        // gh (split layout)
        ln_kernel<<<NROWS, 128>>>(gx, ln1_g + l * D_MODEL, ln1_b + l * D_MODEL, gh);

        // qkv = h @ Wqkv   (A split, B split)
        launch_mg<128, M_PLAIN, true, true, false>(
            gh, D_MODEL, 0, 0,
            gws + OFF_QKV + (long)l * 3 * D_MODEL * D_MODEL, D_MODEL, 0, 0,
            gqkv, 3 * D_MODEL, 0, 0,
            NROWS, 3 * D_MODEL, D_MODEL, 1, nullptr, nullptr, nullptr, 1.f);

        // V^T per (b,h): [1024,64] -> [64,1024]
        transpose_kernel<<<dim3(2, 32, NB * NHEADS), dim3(32, 8)>>>(
            gqkv + 2 * D_MODEL, 3 * D_MODEL, (long)SEQ * 3 * D_MODEL, DHEAD,
            gvt, SEQ, (long)NHEADS * DHEAD * SEQ, (long)DHEAD * SEQ);

        // sim = q @ k^T * scale  (fp32 operands, in-loop split)
        launch_mg<128, M_PLAIN, false, false, false>(
            gqkv,           3 * D_MODEL, (long)SEQ * 3 * D_MODEL, DHEAD,
            gqkv + D_MODEL, 3 * D_MODEL, (long)SEQ * 3 * D_MODEL, DHEAD,
            gsim, SEQ, (long)NHEADS * SEQ * SEQ, (long)SEQ * SEQ,
            SEQ, SEQ, DHEAD, NB * NHEADS,
            nullptr, nullptr, nullptr, scale);

        // sparsemax in place; output in split layout
        sparsemax_kernel<<<NB * NHEADS * SEQ / 8, 256>>>(gsim);

        // ao = attn @ v   (A split; epilogue emits split layout for Wout)
        launch_mg<64, M_PLAIN, false, true, true>(
            gsim, SEQ, (long)NHEADS * SEQ * SEQ, (long)SEQ * SEQ,
            gvt,  SEQ, (long)NHEADS * DHEAD * SEQ, (long)DHEAD * SEQ,
            gao, D_MODEL, (long)SEQ * D_MODEL, DHEAD,
            SEQ, DHEAD, SEQ, NB * NHEADS,
            nullptr, nullptr, nullptr, 1.f);

        // x = x + ao @ Wout + bout   (A split, B split)
        launch_mg<128, M_PLAIN, true, true, false>(
            gao, D_MODEL, 0, 0,
            gws + OFF_WOUT + (long)l * D_MODEL * D_MODEL, D_MODEL, 0, 0,
            gx, D_MODEL, 0, 0, NROWS, D_MODEL, D_MODEL, 1,
            bout + l * D_MODEL, gx, nullptr, 1.f);

        // gh (split layout)
        ln_kernel<<<NROWS, 128>>>(gx, ln2_g + l * D_MODEL, ln2_b + l * D_MODEL, gh);

        // ffg = GEGLU(h @ W1 + b1)   (A split, B split, fused epilogue)
        launch_mg<128, M_GEGLU, true, true, false>(
            gh, D_MODEL, 0, 0,
            gws + OFF_W1 + (long)l * 2 * FF * D_MODEL, D_MODEL, 0, 0,
            gffg, FF, 0, 0, NROWS, 2 * FF, D_MODEL, 1,
            b1 + (long)l * 2 * FF, nullptr, nullptr, 1.f);

        // x = x + ffg @ W2 + b2   (B split; A fp32 in-loop)
        launch_mg<128, M_PLAIN, true, false, false>(
            gffg, FF, 0, 0,
            gws + OFF_W2 + (long)l * D_MODEL * FF, FF, 0, 0,
            gx, D_MODEL, 0, 0, NROWS, D_MODEL, FF, 1,
            b2 + l * D_MODEL, gx, nullptr, 1.f);
    }

    pool1_kernel<<<dim3(NB, 8), 512>>>(gx, gpool);
    pool2_kernel<<<16, 256>>>(gpool, out);
}

// round 11
// speedup vs baseline: 1.0303x; 1.0303x over previous
#include <cuda_runtime.h>
#include <cmath>
#include <cstdint>

#define D_MODEL 512
#define SEQ     1024
#define NB      8
#define NHEADS  8
#define DHEAD   64
#define FF      2048
#define NROWS   (NB*SEQ)    /* 8192 */
#define NDEPTH  3

// ---------------- scratch (device globals; no allocation allowed) ----------
__device__ float g_x   [NROWS * D_MODEL];
__device__ float g_h   [NROWS * D_MODEL];          // split-bf16 layout
__device__ float g_qkv [NROWS * 3 * D_MODEL];      // q,k split; v fp32
__device__ float g_sim [67108864];                 // fp32 then split-bf16 in place
__device__ float g_ao  [NROWS * D_MODEL];          // split-bf16 layout
__device__ float g_ffg [NROWS * FF];
__device__ float g_pool[NB * 8 * D_MODEL];
__device__ float g_wt  [12845056];                 // transposed weights (fp32)
__device__ float g_ws  [12845056];                 // split bf16 weight planes
__device__ float g_vt  [NB * NHEADS * DHEAD * SEQ];// V^T per (b,h): [64][1024]

#define OFF_PROJ 0
#define OFF_QKV  262144
#define OFF_WOUT 2621440
#define OFF_W1   3407872
#define OFF_W2   9699328

// GEMM modes
#define M_PLAIN 0
#define M_GEGLU 1
#define M_QKVE  2   /* q/k sections emitted split, v plain */

// ---------------------------------------------------------------------------
// Split layout: per row, per 32-k chunk (32 words = 128B):
//   words [0:16)  = bf16 hi pairs, permuted: position pos(pl),
//   words [16:32) = bf16 lo pairs, same permutation,
// where pl = pair index in chunk (k = chunk*32 + pl*2) and
//   pos(pl) = (pl & 8) | ((pl & 3) << 1) | ((pl >> 2) & 1).
// Consumer thread (g,c), step ks: LDS.64 at chunk + ks*8 + 2c yields
// (pair ks*8+c, pair ks*8+c+4) — the exact mma fragment words — with the
// same conflict-free bank pattern as the fp32 float2 path.
// ---------------------------------------------------------------------------
__device__ __forceinline__ int pairpos(int pl) {
    return (pl & 8) | ((pl & 3) << 1) | ((pl >> 2) & 1);
}

__device__ __forceinline__ void cp16(uint32_t sa, const float* ga) {
    asm volatile("cp.async.cg.shared.global [%0], [%1], 16;" :: "r"(sa), "l"(ga) : "memory");
}
__device__ __forceinline__ uint32_t smem_u32(const void* p) {
    uint32_t a;
    asm("{ .reg .u64 t; cvta.to.shared.u64 t, %1; cvt.u32.u64 %0, t; }"
        : "=r"(a) : "l"(p));
    return a;
}
__device__ __forceinline__ void cp_commit() {
    asm volatile("cp.async.commit_group;" ::: "memory");
}
// bf16x3 MMA: m16n8k16, row.col, f32 accum
__device__ __forceinline__ void mma16(float* d, const uint32_t* a, const uint32_t* b) {
    asm volatile(
        "mma.sync.aligned.m16n8k16.row.col.f32.bf16.bf16.f32 "
        "{%0,%1,%2,%3}, {%4,%5,%6,%7}, {%8,%9}, {%0,%1,%2,%3};"
        : "+f"(d[0]), "+f"(d[1]), "+f"(d[2]), "+f"(d[3])
        : "r"(a[0]), "r"(a[1]), "r"(a[2]), "r"(a[3]), "r"(b[0]), "r"(b[1]));
}
// split float2 -> packed bf16 hi pair + packed bf16 lo pair
__device__ __forceinline__ void split2(float2 v, uint32_t& hi, uint32_t& lo) {
    asm("cvt.rn.bf16x2.f32 %0, %1, %2;" : "=r"(hi) : "f"(v.y), "f"(v.x));
    const float h0 = __uint_as_float(hi << 16);
    const float h1 = __uint_as_float(hi & 0xFFFF0000u);
    const float r0 = v.x - h0;
    const float r1 = v.y - h1;
    asm("cvt.rn.bf16x2.f32 %0, %1, %2;" : "=r"(lo) : "f"(r1), "f"(r0));
}

// ---------------------------------------------------------------------------
// bf16x3 mma.sync GEMM:  C[M,N] = alpha * A[M,K] @ Bt[N,K]^T (+bias+resid+pos)
//   ASPLIT / BSPLIT: operand is in permuted split layout (LDS.64 fragments).
//   OSPLIT: PLAIN epilogue emits C in split layout (alpha applied, no bias).
//   M_QKVE: cols < 2*D_MODEL emitted split, rest plain (QKV output).
//   M_GEGLU: B cols interleaved (a0,g0,...); stores (a+ba)*gelu(g+bg).
// ---------------------------------------------------------------------------
template<int BN, int MODE, bool BSPLIT, bool ASPLIT, bool OSPLIT>
__global__ void __launch_bounds__(256, 2)
mgemm_kernel(const float* __restrict__ A, long lda, long aO, long aI,
             const float* __restrict__ B, long ldb, long bO, long bI,
             float* __restrict__ C, long ldc, long cO, long cI,
             int K,
             const float* __restrict__ bias,
             const float* __restrict__ resid,
             const float* __restrict__ pos,
             float alpha)
{
    constexpr int BM = 128;
    constexpr int WN = BN / 2;       // warp tile: 32 x WN (4x2 warp grid)
    constexpr int NI = WN / 8;       // n-tiles per warp
    constexpr int PITCH = 40;        // floats per smem row (160B)
    constexpr int STAGE_F = (BM + BN) * PITCH;

    extern __shared__ float smem[];

    const int z = blockIdx.z, zo = z >> 3, zi = z & 7;
    A += zo * aO + zi * aI;
    B += zo * bO + zi * bI;
    C += zo * cO + zi * cI;
    const float* Rz = resid ? resid + zo * cO + zi * cI : nullptr;

    const long m0 = (long)blockIdx.y * BM;
    const long n0 = (long)blockIdx.x * BN;
    A += m0 * lda;
    B += n0 * ldb;

    const int t    = threadIdx.x;
    const int wid  = t >> 5, lane = t & 31;
    const int wr   = wid & 3, wc = wid >> 2;
    const int g    = lane >> 2, c = lane & 3;

    const uint32_t sbase = smem_u32(smem);
    const int niter = K >> 5;        // chunks of K=32

    auto load_stage = [&](int s, int kc) {
        const uint32_t sA = sbase + (uint32_t)(s * STAGE_F) * 4u;
        const uint32_t sB = sA + BM * PITCH * 4u;
        const float* ga = A + kc * 32;
        const float* gb = B + kc * 32;   // 128B per 32-k chunk in both layouts
        const int r0  = t >> 3;
        const int seg = (t & 7) * 16;
#pragma unroll
        for (int p = 0; p < BM / 32; ++p) {
            const int r = p * 32 + r0;
            cp16(sA + r * 160 + seg, ga + (long)r * lda + (t & 7) * 4);
        }
#pragma unroll
        for (int p = 0; p < BN / 32; ++p) {
            const int r = p * 32 + r0;
            cp16(sB + r * 160 + seg, gb + (long)r * ldb + (t & 7) * 4);
        }
        cp_commit();
    };

    float acc[2][NI][4];
#pragma unroll
    for (int mi = 0; mi < 2; ++mi)
#pragma unroll
        for (int ni = 0; ni < NI; ++ni)
#pragma unroll
            for (int j = 0; j < 4; ++j) acc[mi][ni][j] = 0.f;

    load_stage(0, 0);

    for (int i = 0; i < niter; ++i) {
        if (i + 1 < niter) {
            load_stage((i + 1) & 1, i + 1);
            asm volatile("cp.async.wait_group 1;" ::: "memory");
        } else {
            asm volatile("cp.async.wait_group 0;" ::: "memory");
        }
        __syncthreads();

        const float* As = smem + (i & 1) * STAGE_F;
        const float* Bs = As + BM * PITCH;
        const uint32_t* Au = (const uint32_t*)As;
        const uint32_t* Bu = (const uint32_t*)Bs;

#pragma unroll
        for (int ks = 0; ks < 2; ++ks) {      // two k16 steps per K=32 chunk
            const int kk = ks * 16 + 2 * c;
            uint32_t ah[2][4], al[2][4];
#pragma unroll
            for (int mi = 0; mi < 2; ++mi) {
                if (ASPLIT) {
                    const int rb2 = (wr * 32 + mi * 16 + g) * PITCH + ks * 8 + 2 * c;
                    uint2 h0 = *(const uint2*)&Au[rb2];
                    uint2 h1 = *(const uint2*)&Au[rb2 + 8 * PITCH];
                    uint2 l0 = *(const uint2*)&Au[rb2 + 16];
                    uint2 l1 = *(const uint2*)&Au[rb2 + 8 * PITCH + 16];
                    ah[mi][0] = h0.x; ah[mi][2] = h0.y;
                    ah[mi][1] = h1.x; ah[mi][3] = h1.y;
                    al[mi][0] = l0.x; al[mi][2] = l0.y;
                    al[mi][1] = l1.x; al[mi][3] = l1.y;
                } else {
                    const int rb = (wr * 32 + mi * 16 + g) * PITCH + kk;
                    split2(*(const float2*)&As[rb],                 ah[mi][0], al[mi][0]);
                    split2(*(const float2*)&As[rb + 8 * PITCH],     ah[mi][1], al[mi][1]);
                    split2(*(const float2*)&As[rb + 8],             ah[mi][2], al[mi][2]);
                    split2(*(const float2*)&As[rb + 8 * PITCH + 8], ah[mi][3], al[mi][3]);
                }
            }
            uint32_t bh[NI][2], bl[NI][2];
#pragma unroll
            for (int ni = 0; ni < NI; ++ni) {
                if (BSPLIT) {
                    const int rb2 = (wc * WN + ni * 8 + g) * PITCH + ks * 8 + 2 * c;
                    uint2 h = *(const uint2*)&Bu[rb2];
                    uint2 l = *(const uint2*)&Bu[rb2 + 16];
                    bh[ni][0] = h.x; bh[ni][1] = h.y;
                    bl[ni][0] = l.x; bl[ni][1] = l.y;
                } else {
                    const int rb = (wc * WN + ni * 8 + g) * PITCH + kk;
                    split2(*(const float2*)&Bs[rb],     bh[ni][0], bl[ni][0]);
                    split2(*(const float2*)&Bs[rb + 8], bh[ni][1], bl[ni][1]);
                }
            }
#pragma unroll
            for (int mi = 0; mi < 2; ++mi)
#pragma unroll
                for (int ni = 0; ni < NI; ++ni) {
                    mma16(acc[mi][ni], al[mi], bh[ni]);
                    mma16(acc[mi][ni], ah[mi], bl[ni]);
                    mma16(acc[mi][ni], ah[mi], bh[ni]);
                }
        }
        __syncthreads();
    }

    // ---- epilogue ----
#pragma unroll
    for (int mi = 0; mi < 2; ++mi) {
#pragma unroll
        for (int ni = 0; ni < NI; ++ni) {
            const long col = n0 + wc * WN + ni * 8 + 2 * c;
#pragma unroll
            for (int h = 0; h < 2; ++h) {
                const long row = m0 + wr * 32 + mi * 16 + g + h * 8;
                float vx = acc[mi][ni][2 * h];
                float vy = acc[mi][ni][2 * h + 1];
                if (MODE == M_GEGLU) {
                    const long j = col >> 1;
                    const float a  = vx + bias[j];
                    const float gg = vy + bias[j + FF];
                    C[row * ldc + j] = a * gg * normcdff(gg);
                } else if (OSPLIT || (MODE == M_QKVE && col < 2 * D_MODEL)) {
                    uint32_t hi, lo;
                    split2(make_float2(vx * alpha, vy * alpha), hi, lo);
                    const int pp = pairpos((int)((col >> 1) & 15));
                    const long po = row * ldc + ((col >> 5) << 5) + pp;
                    ((uint32_t*)C)[po]      = hi;
                    ((uint32_t*)C)[po + 16] = lo;
                } else {
                    vx *= alpha; vy *= alpha;
                    if (bias) {
                        float2 bv = *(const float2*)&bias[col];
                        vx += bv.x; vy += bv.y;
                    }
                    const long off = row * ldc + col;
                    if (Rz) {
                        float2 rv = *(const float2*)&Rz[off];
                        vx += rv.x; vy += rv.y;
                    }
                    if (pos) {
                        float2 pv = *(const float2*)&pos[(row & (SEQ - 1)) * D_MODEL + col];
                        vx += pv.x; vy += pv.y;
                    }
                    *(float2*)&C[off] = make_float2(vx, vy);
                }
            }
        }
    }
}

// ---------------------------------------------------------------------------
// Convert fp32 [N,K] row-major -> permuted split bf16 layout.
// ---------------------------------------------------------------------------
__global__ void __launch_bounds__(256)
split_weights_kernel(const float* __restrict__ in, uint32_t* __restrict__ out,
                     int K, long total_pairs)
{
    const long idx = (long)blockIdx.x * 256 + threadIdx.x;
    if (idx >= total_pairs) return;
    const int  kp   = K >> 1;
    const long row  = idx / kp;
    const int  pid  = (int)(idx - row * kp);
    const int  kc   = pid >> 4;
    const int  pl   = pid & 15;
    const int  k0   = kc * 32 + pl * 2;
    float2 v = *(const float2*)&in[row * K + k0];
    uint32_t hi, lo;
    split2(v, hi, lo);
    const int pp = pairpos(pl);
    out[row * K + kc * 32 + pp]      = hi;
    out[row * K + kc * 32 + 16 + pp] = lo;
}

// ---------------------------------------------------------------------------
__global__ void __launch_bounds__(256)
transpose_kernel(const float* __restrict__ in, long ldi, long iO, long iI,
                 float* __restrict__ out, long ldo, long oO, long oI)
{
    __shared__ float tile[32][33];
    const int z = blockIdx.z;
    in  += (z >> 3) * iO + (z & 7) * iI;
    out += (z >> 3) * oO + (z & 7) * oI;
    const long r0 = (long)blockIdx.y * 32, c0 = (long)blockIdx.x * 32;
#pragma unroll
    for (int i = 0; i < 32; i += 8)
        tile[threadIdx.y + i][threadIdx.x] =
            in[(r0 + threadIdx.y + i) * ldi + c0 + threadIdx.x];
    __syncthreads();
#pragma unroll
    for (int i = 0; i < 32; i += 8)
        out[(c0 + threadIdx.y + i) * ldo + r0 + threadIdx.x] =
            tile[threadIdx.x][threadIdx.y + i];
}

// W1 transpose with a/g interleave
__global__ void __launch_bounds__(256)
transpose_w1_kernel(const float* __restrict__ in, float* __restrict__ out)
{
    __shared__ float tile[32][33];
    const int z = blockIdx.z;
    in  += (long)z * D_MODEL * (2 * FF);
    out += (long)z * (2 * FF) * D_MODEL;
    const long r0 = (long)blockIdx.y * 32;
    const long c0 = (long)blockIdx.x * 32;
#pragma unroll
    for (int i = 0; i < 32; i += 8)
        tile[threadIdx.y + i][threadIdx.x] =
            in[(r0 + threadIdx.y + i) * (2 * FF) + c0 + threadIdx.x];
    __syncthreads();
#pragma unroll
    for (int i = 0; i < 32; i += 8) {
        const long n = c0 + threadIdx.y + i;
        const long r_out = (n < FF) ? 2 * n : 2 * (n - FF) + 1;
        out[r_out * D_MODEL + r0 + threadIdx.x] = tile[threadIdx.x][threadIdx.y + i];
    }
}

// ---------------------------------------------------------------------------
// LayerNorm; output in permuted split-bf16 layout (consumed only as GEMM A).
// ---------------------------------------------------------------------------
__global__ void __launch_bounds__(128)
ln_kernel(const float* __restrict__ x, const float* __restrict__ g,
          const float* __restrict__ b, float* __restrict__ o)
{
    __shared__ float sh[4];
    const long row = blockIdx.x;
    const int  t   = threadIdx.x;
    float4 v = ((const float4*)(x + row * D_MODEL))[t];

    float s = v.x + v.y + v.z + v.w;
#pragma unroll
    for (int off = 16; off; off >>= 1) s += __shfl_xor_sync(~0u, s, off);
    if ((t & 31) == 0) sh[t >> 5] = s;
    __syncthreads();
    const float mu = (sh[0] + sh[1] + sh[2] + sh[3]) * (1.f / D_MODEL);

    const float dx = v.x - mu, dy = v.y - mu, dz = v.z - mu, dw = v.w - mu;
    float s2 = dx * dx + dy * dy + dz * dz + dw * dw;
#pragma unroll
    for (int off = 16; off; off >>= 1) s2 += __shfl_xor_sync(~0u, s2, off);
    __syncthreads();
    if ((t & 31) == 0) sh[t >> 5] = s2;
    __syncthreads();
    const float var = (sh[0] + sh[1] + sh[2] + sh[3]) * (1.f / D_MODEL);
    const float r   = rsqrtf(var + 1e-5f);

    float4 gg = ((const float4*)g)[t];
    float4 bb = ((const float4*)b)[t];
    float4 ov;
    ov.x = dx * r * gg.x + bb.x;
    ov.y = dy * r * gg.y + bb.y;
    ov.z = dz * r * gg.z + bb.z;
    ov.w = dw * r * gg.w + bb.w;

    uint32_t h0, l0, h1, l1;
    split2(make_float2(ov.x, ov.y), h0, l0);
    split2(make_float2(ov.z, ov.w), h1, l1);
    uint32_t* orow = (uint32_t*)(o + row * D_MODEL);
    const int cb  = (t >> 3) * 32;
    const int pl0 = (2 * t) & 15;
    orow[cb + pairpos(pl0)]          = h0;
    orow[cb + pairpos(pl0 + 1)]      = h1;
    orow[cb + 16 + pairpos(pl0)]     = l0;
    orow[cb + 16 + pairpos(pl0 + 1)] = l1;
}

// ---------------------------------------------------------------------------
// Sparsemax, warp-per-row; 15-iter bisection + exact Michelot refinement.
// Output written IN PLACE in permuted split-bf16 layout.
// ---------------------------------------------------------------------------
__global__ void __launch_bounds__(256)
sparsemax_kernel(float* __restrict__ sim)
{
    const long row  = (long)blockIdx.x * 8 + (threadIdx.x >> 5);
    const int  lane = threadIdx.x & 31;
    float4* base = (float4*)(sim + row * (long)SEQ);

    float4 z[8];
#pragma unroll
    for (int j = 0; j < 8; ++j) z[j] = base[j * 32 + lane];

    float m = -1e30f;
#pragma unroll
    for (int j = 0; j < 8; ++j)
        m = fmaxf(m, fmaxf(fmaxf(z[j].x, z[j].y), fmaxf(z[j].z, z[j].w)));
#pragma unroll
    for (int off = 16; off; off >>= 1) m = fmaxf(m, __shfl_xor_sync(~0u, m, off));

    float lo = m - 1.f, hi = m;
#pragma unroll 1
    for (int it = 0; it < 15; ++it) {
        const float tau = 0.5f * (lo + hi);
        float s = 0.f;
#pragma unroll
        for (int j = 0; j < 8; ++j) {
            s += fmaxf(z[j].x - tau, 0.f) + fmaxf(z[j].y - tau, 0.f)
               + fmaxf(z[j].z - tau, 0.f) + fmaxf(z[j].w - tau, 0.f);
        }
#pragma unroll
        for (int off = 16; off; off >>= 1) s += __shfl_xor_sync(~0u, s, off);
        if (s >= 1.f) lo = tau; else hi = tau;
    }
    {
        const float tau = 0.5f * (lo + hi);
        float s = 0.f, k = 0.f;
#pragma unroll
        for (int j = 0; j < 8; ++j) {
            if (z[j].x > tau) { s += z[j].x; k += 1.f; }
            if (z[j].y > tau) { s += z[j].y; k += 1.f; }
            if (z[j].z > tau) { s += z[j].z; k += 1.f; }
            if (z[j].w > tau) { s += z[j].w; k += 1.f; }
        }
#pragma unroll
        for (int off = 16; off; off >>= 1) {
            s += __shfl_xor_sync(~0u, s, off);
            k += __shfl_xor_sync(~0u, k, off);
        }
        const float tau_x = (s - 1.f) / k;
        uint32_t* orow = (uint32_t*)(sim + row * (long)SEQ);
#pragma unroll
        for (int j = 0; j < 8; ++j) {
            const float ox = fmaxf(z[j].x - tau_x, 0.f);
            const float oy = fmaxf(z[j].y - tau_x, 0.f);
            const float oz = fmaxf(z[j].z - tau_x, 0.f);
            const float ow = fmaxf(z[j].w - tau_x, 0.f);
            uint32_t h0, l0, h1, l1;
            split2(make_float2(ox, oy), h0, l0);
            split2(make_float2(oz, ow), h1, l1);
            const int q   = j * 32 + lane;          // float4 index in row
            const int cb  = (q >> 3) * 32;
            const int pl0 = (2 * q) & 15;
            orow[cb + pairpos(pl0)]          = h0;
            orow[cb + pairpos(pl0 + 1)]      = h1;
            orow[cb + 16 + pairpos(pl0)]     = l0;
            orow[cb + 16 + pairpos(pl0 + 1)] = l1;
        }
    }
}

// ---------------------------------------------------------------------------
__global__ void __launch_bounds__(512)
pool1_kernel(const float* __restrict__ x, float* __restrict__ p)
{
    const int b = blockIdx.x, cc = blockIdx.y;
    const int d = threadIdx.x;
    float s = 0.f;
    const float* base = x + ((long)b * SEQ + cc * 128) * D_MODEL + d;
    for (int i = 0; i < 128; ++i) s += base[(long)i * D_MODEL];
    p[(b * 8 + cc) * D_MODEL + d] = s;
}

__global__ void __launch_bounds__(256)
pool2_kernel(const float* __restrict__ p, float* __restrict__ o)
{
    const int i = blockIdx.x * blockDim.x + threadIdx.x;
    const int b = i >> 9, d = i & 511;
    float s = 0.f;
#pragma unroll
    for (int cc = 0; cc < 8; ++cc) s += p[(b * 8 + cc) * D_MODEL + d];
    o[i] = s * (1.f / SEQ);
}

// ---------------------------------------------------------------------------
#define SMEM_BN128 (2 * (128 + 128) * 160)
#define SMEM_BN64  (2 * (128 +  64) * 160)

template<int BN, int MODE, bool BSPLIT, bool ASPLIT, bool OSPLIT>
static void launch_mg(const float* A, long lda, long aO, long aI,
                      const float* B, long ldb, long bO, long bI,
                      float* C, long ldc, long cO, long cI,
                      int M, int N, int K, int batches,
                      const float* bias, const float* resid,
                      const float* pos, float alpha)
{
    dim3 grid(N / BN, M / 128, batches);
    const int smem = (BN == 128) ? SMEM_BN128 : SMEM_BN64;
    mgemm_kernel<BN, MODE, BSPLIT, ASPLIT, OSPLIT><<<grid, 256, smem>>>(
        A, lda, aO, aI, B, ldb, bO, bI, C, ldc, cO, cI, K, bias, resid, pos, alpha);
}

extern "C" void kernel_launch(void* const* d_in, const int* in_sizes, int n_in,
                              void* d_out, int out_size)
{
    const float* x      = (const float*)d_in[0];
    const float* proj_w = (const float*)d_in[1];
    const float* proj_b = (const float*)d_in[2];
    const float* pos    = (const float*)d_in[3];
    const float* ln1_g  = (const float*)d_in[4];
    const float* ln1_b  = (const float*)d_in[5];
    const float* wqkv   = (const float*)d_in[6];
    const float* wout   = (const float*)d_in[7];
    const float* bout   = (const float*)d_in[8];
    const float* ln2_g  = (const float*)d_in[9];
    const float* ln2_b  = (const float*)d_in[10];
    const float* w1     = (const float*)d_in[11];
    const float* b1     = (const float*)d_in[12];
    const float* w2     = (const float*)d_in[13];
    const float* b2     = (const float*)d_in[14];
    float* out = (float*)d_out;

    cudaFuncSetAttribute((const void*)mgemm_kernel<128, M_PLAIN, true, false, false>,
                         cudaFuncAttributeMaxDynamicSharedMemorySize, SMEM_BN128);
    cudaFuncSetAttribute((const void*)mgemm_kernel<128, M_QKVE, true, true, false>,
                         cudaFuncAttributeMaxDynamicSharedMemorySize, SMEM_BN128);
    cudaFuncSetAttribute((const void*)mgemm_kernel<128, M_PLAIN, true, true, false>,
                         cudaFuncAttributeMaxDynamicSharedMemorySize, SMEM_BN128);
    cudaFuncSetAttribute((const void*)mgemm_kernel<128, M_GEGLU, true, true, false>,
                         cudaFuncAttributeMaxDynamicSharedMemorySize, SMEM_BN128);
    cudaFuncSetAttribute((const void*)mgemm_kernel<64, M_PLAIN, false, true, true>,
                         cudaFuncAttributeMaxDynamicSharedMemorySize, SMEM_BN64);

    float *gx, *gh, *gqkv, *gsim, *gao, *gffg, *gpool, *gwt, *gws, *gvt;
    cudaGetSymbolAddress((void**)&gx,    g_x);
    cudaGetSymbolAddress((void**)&gh,    g_h);
    cudaGetSymbolAddress((void**)&gqkv,  g_qkv);
    cudaGetSymbolAddress((void**)&gsim,  g_sim);
    cudaGetSymbolAddress((void**)&gao,   g_ao);
    cudaGetSymbolAddress((void**)&gffg,  g_ffg);
    cudaGetSymbolAddress((void**)&gpool, g_pool);
    cudaGetSymbolAddress((void**)&gwt,   g_wt);
    cudaGetSymbolAddress((void**)&gws,   g_ws);
    cudaGetSymbolAddress((void**)&gvt,   g_vt);

    // ---- weight transposes (B operands as [N,K] row-major, fp32) ----
    transpose_kernel<<<dim3(16, 16, 1), dim3(32, 8)>>>(
        proj_w, D_MODEL, 0, 0, gwt + OFF_PROJ, D_MODEL, 0, 0);
    transpose_kernel<<<dim3(48, 16, 3), dim3(32, 8)>>>(
        wqkv, 3 * D_MODEL, 0, (long)D_MODEL * 3 * D_MODEL,
        gwt + OFF_QKV, D_MODEL, 0, (long)3 * D_MODEL * D_MODEL);
    transpose_kernel<<<dim3(16, 16, 3), dim3(32, 8)>>>(
        wout, D_MODEL, 0, (long)D_MODEL * D_MODEL,
        gwt + OFF_WOUT, D_MODEL, 0, (long)D_MODEL * D_MODEL);
    transpose_w1_kernel<<<dim3(128, 16, 3), dim3(32, 8)>>>(w1, gwt + OFF_W1);
    transpose_kernel<<<dim3(16, 64, 3), dim3(32, 8)>>>(
        w2, D_MODEL, 0, (long)FF * D_MODEL,
        gwt + OFF_W2, FF, 0, (long)D_MODEL * FF);

    // ---- pre-split all weights (permuted split layout) ----
    {
        long pairs = (long)512 * 256;
        split_weights_kernel<<<(pairs + 255) / 256, 256>>>(
            gwt + OFF_PROJ, (uint32_t*)(gws + OFF_PROJ), 512, pairs);
        pairs = (long)3 * 1536 * 256;
        split_weights_kernel<<<(pairs + 255) / 256, 256>>>(
            gwt + OFF_QKV, (uint32_t*)(gws + OFF_QKV), 512, pairs);
        pairs = (long)3 * 512 * 256;
        split_weights_kernel<<<(pairs + 255) / 256, 256>>>(
            gwt + OFF_WOUT, (uint32_t*)(gws + OFF_WOUT), 512, pairs);
        pairs = (long)3 * 4096 * 256;
        split_weights_kernel<<<(pairs + 255) / 256, 256>>>(
            gwt + OFF_W1, (uint32_t*)(gws + OFF_W1), 512, pairs);
        pairs = (long)3 * 512 * 1024;
        split_weights_kernel<<<(pairs + 255) / 256, 256>>>(
            gwt + OFF_W2, (uint32_t*)(gws + OFF_W2), 2048, pairs);
    }

    // x = x @ proj_w + proj_b + pos   (A fp32 in-loop, B split)
    launch_mg<128, M_PLAIN, true, false, false>(
        x, D_MODEL, 0, 0, gws + OFF_PROJ, D_MODEL, 0, 0,
        gx, D_MODEL, 0, 0, NROWS, D_MODEL, D_MODEL, 1,
        proj_b, nullptr, pos, 1.f);

    const float scale = 0.125f;

    for (int l = 0; l < NDEPTH; ++l) {
        // gh (split layout)
        ln_kernel<<<NROWS, 128>>>(gx, ln1_g + l * D_MODEL, ln1_b + l * D_MODEL, gh);

        // qkv = h @ Wqkv; q/k emitted split, v plain
        launch_mg<128, M_QKVE, true, true, false>(
            gh, D_MODEL, 0, 0,
            gws + OFF_QKV + (long)l * 3 * D_MODEL * D_MODEL, D_MODEL, 0, 0,
            gqkv, 3 * D_MODEL, 0, 0,
            NROWS, 3 * D_MODEL, D_MODEL, 1, nullptr, nullptr, nullptr, 1.f);

        // V^T per (b,h): [1024,64] -> [64,1024]  (v is plain fp32)
        transpose_kernel<<<dim3(2, 32, NB * NHEADS), dim3(32, 8)>>>(
            gqkv + 2 * D_MODEL, 3 * D_MODEL, (long)SEQ * 3 * D_MODEL, DHEAD,
            gvt, SEQ, (long)NHEADS * DHEAD * SEQ, (long)DHEAD * SEQ);

        // sim = q @ k^T * scale   (A split, B split; C plain fp32)
        launch_mg<128, M_PLAIN, true, true, false>(
            gqkv,           3 * D_MODEL, (long)SEQ * 3 * D_MODEL, DHEAD,
            gqkv + D_MODEL, 3 * D_MODEL, (long)SEQ * 3 * D_MODEL, DHEAD,
            gsim, SEQ, (long)NHEADS * SEQ * SEQ, (long)SEQ * SEQ,
            SEQ, SEQ, DHEAD, NB * NHEADS,
            nullptr, nullptr, nullptr, scale);

        // sparsemax in place; output split layout
        sparsemax_kernel<<<NB * NHEADS * SEQ / 8, 256>>>(gsim);

        // ao = attn @ v   (A split, B fp32 in-loop; OSPLIT out)
        launch_mg<64, M_PLAIN, false, true, true>(
            gsim, SEQ, (long)NHEADS * SEQ * SEQ, (long)SEQ * SEQ,
            gvt,  SEQ, (long)NHEADS * DHEAD * SEQ, (long)DHEAD * SEQ,
            gao, D_MODEL, (long)SEQ * D_MODEL, DHEAD,
            SEQ, DHEAD, SEQ, NB * NHEADS,
            nullptr, nullptr, nullptr, 1.f);

        // x = x + ao @ Wout + bout   (A split, B split)
        launch_mg<128, M_PLAIN, true, true, false>(
            gao, D_MODEL, 0, 0,
            gws + OFF_WOUT + (long)l * D_MODEL * D_MODEL, D_MODEL, 0, 0,
            gx, D_MODEL, 0, 0, NROWS, D_MODEL, D_MODEL, 1,
            bout + l * D_MODEL, gx, nullptr, 1.f);

        // gh (split layout)
        ln_kernel<<<NROWS, 128>>>(gx, ln2_g + l * D_MODEL, ln2_b + l * D_MODEL, gh);

        // ffg = GEGLU(h @ W1 + b1)   (A split, B split, fused epilogue)
        launch_mg<128, M_GEGLU, true, true, false>(
            gh, D_MODEL, 0, 0,
            gws + OFF_W1 + (long)l * 2 * FF * D_MODEL, D_MODEL, 0, 0,
            gffg, FF, 0, 0, NROWS, 2 * FF, D_MODEL, 1,
            b1 + (long)l * 2 * FF, nullptr, nullptr, 1.f);

        // x = x + ffg @ W2 + b2   (A fp32 in-loop, B split)
        launch_mg<128, M_PLAIN, true, false, false>(
            gffg, FF, 0, 0,
            gws + OFF_W2 + (long)l * D_MODEL * FF, FF, 0, 0,
            gx, D_MODEL, 0, 0, NROWS, D_MODEL, FF, 1,
            b2 + l * D_MODEL, gx, nullptr, 1.f);
    }

    pool1_kernel<<<dim3(NB, 8), 512>>>(gx, gpool);
    pool2_kernel<<<16, 256>>>(gpool, out);
}

// round 12
// speedup vs baseline: 1.0357x; 1.0052x over previous
#include <cuda_runtime.h>
#include <cmath>
#include <cstdint>

#define D_MODEL 512
#define SEQ     1024
#define NB      8
#define NHEADS  8
#define DHEAD   64
#define FF      2048
#define NROWS   (NB*SEQ)    /* 8192 */
#define NDEPTH  3

// ---------------- scratch (device globals; no allocation allowed) ----------
__device__ float g_x   [NROWS * D_MODEL];
__device__ float g_h   [NROWS * D_MODEL];          // split-bf16 layout
__device__ float g_qkv [NROWS * 3 * D_MODEL];
__device__ float g_sim [67108864];                 // fp32 scores (read-only after QKT)
__device__ float g_tau [NB * NHEADS * SEQ];        // sparsemax thresholds
__device__ float g_ao  [NROWS * D_MODEL];
__device__ float g_ffg [NROWS * FF];
__device__ float g_pool[NB * 8 * D_MODEL];
__device__ float g_wt  [12845056];                 // transposed weights (fp32)
__device__ float g_ws  [12845056];                 // split bf16 hi/lo weight planes
__device__ float g_vt  [NB * NHEADS * DHEAD * SEQ];// V^T per (b,h): [64][1024]

#define OFF_PROJ 0
#define OFF_QKV  262144
#define OFF_WOUT 2621440
#define OFF_W1   3407872
#define OFF_W2   9699328

// GEMM modes
#define M_PLAIN 0
#define M_GEGLU 1
#define M_SPAPP 2   /* apply max(a - tau_row, 0) to A before split */

// ---------------------------------------------------------------------------
__device__ __forceinline__ void cp16(uint32_t sa, const float* ga) {
    asm volatile("cp.async.cg.shared.global [%0], [%1], 16;" :: "r"(sa), "l"(ga) : "memory");
}
__device__ __forceinline__ uint32_t smem_u32(const void* p) {
    uint32_t a;
    asm("{ .reg .u64 t; cvta.to.shared.u64 t, %1; cvt.u32.u64 %0, t; }"
        : "=r"(a) : "l"(p));
    return a;
}
__device__ __forceinline__ void cp_commit() {
    asm volatile("cp.async.commit_group;" ::: "memory");
}
// bf16x3 MMA: m16n8k16, row.col, f32 accum
__device__ __forceinline__ void mma16(float* d, const uint32_t* a, const uint32_t* b) {
    asm volatile(
        "mma.sync.aligned.m16n8k16.row.col.f32.bf16.bf16.f32 "
        "{%0,%1,%2,%3}, {%4,%5,%6,%7}, {%8,%9}, {%0,%1,%2,%3};"
        : "+f"(d[0]), "+f"(d[1]), "+f"(d[2]), "+f"(d[3])
        : "r"(a[0]), "r"(a[1]), "r"(a[2]), "r"(a[3]), "r"(b[0]), "r"(b[1]));
}
// split float2 -> packed bf16 hi pair + packed bf16 lo pair
__device__ __forceinline__ void split2(float2 v, uint32_t& hi, uint32_t& lo) {
    asm("cvt.rn.bf16x2.f32 %0, %1, %2;" : "=r"(hi) : "f"(v.y), "f"(v.x));
    const float h0 = __uint_as_float(hi << 16);
    const float h1 = __uint_as_float(hi & 0xFFFF0000u);
    const float r0 = v.x - h0;
    const float r1 = v.y - h1;
    asm("cvt.rn.bf16x2.f32 %0, %1, %2;" : "=r"(lo) : "f"(r1), "f"(r0));
}

// ---------------------------------------------------------------------------
// bf16x3 mma.sync GEMM:  C[M,N] = alpha * A[M,K] @ Bt[N,K]^T (+bias+resid+pos)
// BSPLIT: B is pre-split bf16 (per row, per 32-k chunk: 16 hi words then 16
//   lo words of packed (k,k+1) pairs). Same bytes/row as fp32.
// M_GEGLU: B cols interleaved (a0,g0,...); stores (a+ba)*gelu(g+bg) at
//   C[row, col/2], ldc = FF.
// M_SPAPP: A rows get max(a - tau[row], 0) before the bf16 split (tau from
//   global, indexed z*SEQ + m0 + row).
// ---------------------------------------------------------------------------
template<int BN, int MODE, bool BSPLIT>
__global__ void __launch_bounds__(256, 2)
mgemm_kernel(const float* __restrict__ A, long lda, long aO, long aI,
             const float* __restrict__ B, long ldb, long bO, long bI,
             float* __restrict__ C, long ldc, long cO, long cI,
             int K,
             const float* __restrict__ bias,
             const float* __restrict__ resid,
             const float* __restrict__ pos,
             const float* __restrict__ tau,
             float alpha)
{
    constexpr int BM = 128;
    constexpr int WN = BN / 2;       // warp tile: 32 x WN (4x2 warp grid)
    constexpr int NI = WN / 8;       // n-tiles per warp
    constexpr int PITCH = 40;        // floats per smem row (160B)
    constexpr int STAGE_F = (BM + BN) * PITCH;

    extern __shared__ float smem[];

    const int z = blockIdx.z, zo = z >> 3, zi = z & 7;
    A += zo * aO + zi * aI;
    B += zo * bO + zi * bI;
    C += zo * cO + zi * cI;
    const float* Rz = resid ? resid + zo * cO + zi * cI : nullptr;

    const long m0 = (long)blockIdx.y * BM;
    const long n0 = (long)blockIdx.x * BN;
    A += m0 * lda;
    B += n0 * ldb;

    const int t    = threadIdx.x;
    const int wid  = t >> 5, lane = t & 31;
    const int wr   = wid & 3, wc = wid >> 2;
    const int g    = lane >> 2, c = lane & 3;

    // per-warp sparsemax thresholds (constant over K)
    float taur[2][2] = {{0.f, 0.f}, {0.f, 0.f}};
    if (MODE == M_SPAPP) {
        const float* tb = tau + (long)z * SEQ + m0;
#pragma unroll
        for (int mi = 0; mi < 2; ++mi) {
            taur[mi][0] = tb[wr * 32 + mi * 16 + g];
            taur[mi][1] = tb[wr * 32 + mi * 16 + g + 8];
        }
    }

    const uint32_t sbase = smem_u32(smem);
    const int niter = K >> 5;        // chunks of K=32

    auto load_stage = [&](int s, int kc) {
        const uint32_t sA = sbase + (uint32_t)(s * STAGE_F) * 4u;
        const uint32_t sB = sA + BM * PITCH * 4u;
        const float* ga = A + kc * 32;
        const float* gb = B + kc * 32;
        const int r0  = t >> 3;
        const int seg = (t & 7) * 16;
#pragma unroll
        for (int p = 0; p < BM / 32; ++p) {
            const int r = p * 32 + r0;
            cp16(sA + r * 160 + seg, ga + (long)r * lda + (t & 7) * 4);
        }
#pragma unroll
        for (int p = 0; p < BN / 32; ++p) {
            const int r = p * 32 + r0;
            cp16(sB + r * 160 + seg, gb + (long)r * ldb + (t & 7) * 4);
        }
        cp_commit();
    };

    float acc[2][NI][4];
#pragma unroll
    for (int mi = 0; mi < 2; ++mi)
#pragma unroll
        for (int ni = 0; ni < NI; ++ni)
#pragma unroll
            for (int j = 0; j < 4; ++j) acc[mi][ni][j] = 0.f;

    load_stage(0, 0);

    for (int i = 0; i < niter; ++i) {
        if (i + 1 < niter) {
            load_stage((i + 1) & 1, i + 1);
            asm volatile("cp.async.wait_group 1;" ::: "memory");
        } else {
            asm volatile("cp.async.wait_group 0;" ::: "memory");
        }
        __syncthreads();

        const float* As = smem + (i & 1) * STAGE_F;
        const float* Bs = As + BM * PITCH;
        const uint32_t* Bu = (const uint32_t*)Bs;

#pragma unroll
        for (int ks = 0; ks < 2; ++ks) {      // two k16 steps per K=32 chunk
            const int kk = ks * 16 + 2 * c;
            uint32_t ah[2][4], al[2][4];
#pragma unroll
            for (int mi = 0; mi < 2; ++mi) {
                const int rb = (wr * 32 + mi * 16 + g) * PITCH + kk;
                float2 v0 = *(const float2*)&As[rb];
                float2 v1 = *(const float2*)&As[rb + 8 * PITCH];
                float2 v2 = *(const float2*)&As[rb + 8];
                float2 v3 = *(const float2*)&As[rb + 8 * PITCH + 8];
                if (MODE == M_SPAPP) {
                    const float t0 = taur[mi][0], t1 = taur[mi][1];
                    v0.x = fmaxf(v0.x - t0, 0.f); v0.y = fmaxf(v0.y - t0, 0.f);
                    v1.x = fmaxf(v1.x - t1, 0.f); v1.y = fmaxf(v1.y - t1, 0.f);
                    v2.x = fmaxf(v2.x - t0, 0.f); v2.y = fmaxf(v2.y - t0, 0.f);
                    v3.x = fmaxf(v3.x - t1, 0.f); v3.y = fmaxf(v3.y - t1, 0.f);
                }
                split2(v0, ah[mi][0], al[mi][0]);
                split2(v1, ah[mi][1], al[mi][1]);
                split2(v2, ah[mi][2], al[mi][2]);
                split2(v3, ah[mi][3], al[mi][3]);
            }
            uint32_t bh[NI][2], bl[NI][2];
#pragma unroll
            for (int ni = 0; ni < NI; ++ni) {
                if (BSPLIT) {
                    const int rb2 = (wc * WN + ni * 8 + g) * PITCH + ks * 8 + c;
                    bh[ni][0] = Bu[rb2];
                    bh[ni][1] = Bu[rb2 + 4];
                    bl[ni][0] = Bu[rb2 + 16];
                    bl[ni][1] = Bu[rb2 + 20];
                } else {
                    const int rb = (wc * WN + ni * 8 + g) * PITCH + kk;
                    split2(*(const float2*)&Bs[rb],     bh[ni][0], bl[ni][0]);
                    split2(*(const float2*)&Bs[rb + 8], bh[ni][1], bl[ni][1]);
                }
            }
#pragma unroll
            for (int mi = 0; mi < 2; ++mi)
#pragma unroll
                for (int ni = 0; ni < NI; ++ni) {
                    mma16(acc[mi][ni], al[mi], bh[ni]);
                    mma16(acc[mi][ni], ah[mi], bl[ni]);
                    mma16(acc[mi][ni], ah[mi], bh[ni]);
                }
        }
        __syncthreads();
    }

    // ---- epilogue ----
#pragma unroll
    for (int mi = 0; mi < 2; ++mi) {
#pragma unroll
        for (int ni = 0; ni < NI; ++ni) {
            const long col = n0 + wc * WN + ni * 8 + 2 * c;
#pragma unroll
            for (int h = 0; h < 2; ++h) {
                const long row = m0 + wr * 32 + mi * 16 + g + h * 8;
                float vx = acc[mi][ni][2 * h];
                float vy = acc[mi][ni][2 * h + 1];
                if (MODE == M_GEGLU) {
                    const long j = col >> 1;
                    const float a  = vx + bias[j];
                    const float gg = vy + bias[j + FF];
                    C[row * ldc + j] = a * gg * normcdff(gg);
                } else {
                    vx *= alpha; vy *= alpha;
                    if (bias) {
                        float2 bv = *(const float2*)&bias[col];
                        vx += bv.x; vy += bv.y;
                    }
                    const long off = row * ldc + col;
                    if (Rz) {
                        float2 rv = *(const float2*)&Rz[off];
                        vx += rv.x; vy += rv.y;
                    }
                    if (pos) {
                        float2 pv = *(const float2*)&pos[(row & (SEQ - 1)) * D_MODEL + col];
                        vx += pv.x; vy += pv.y;
                    }
                    *(float2*)&C[off] = make_float2(vx, vy);
                }
            }
        }
    }
}

// ---------------------------------------------------------------------------
// Convert fp32 [N,K] row-major -> split bf16 layout.
// ---------------------------------------------------------------------------
__global__ void __launch_bounds__(256)
split_weights_kernel(const float* __restrict__ in, uint32_t* __restrict__ out,
                     int K, long total_pairs)
{
    const long idx = (long)blockIdx.x * 256 + threadIdx.x;
    if (idx >= total_pairs) return;
    const int  kp   = K >> 1;
    const long row  = idx / kp;
    const int  pid  = (int)(idx - row * kp);
    const int  kc   = pid >> 4;
    const int  pl   = pid & 15;
    const int  k0   = kc * 32 + pl * 2;
    float2 v = *(const float2*)&in[row * K + k0];
    uint32_t hi, lo;
    split2(v, hi, lo);
    out[row * K + kc * 32 + pl]      = hi;
    out[row * K + kc * 32 + 16 + pl] = lo;
}

// ---------------------------------------------------------------------------
__global__ void __launch_bounds__(256)
transpose_kernel(const float* __restrict__ in, long ldi, long iO, long iI,
                 float* __restrict__ out, long ldo, long oO, long oI)
{
    __shared__ float tile[32][33];
    const int z = blockIdx.z;
    in  += (z >> 3) * iO + (z & 7) * iI;
    out += (z >> 3) * oO + (z & 7) * oI;
    const long r0 = (long)blockIdx.y * 32, c0 = (long)blockIdx.x * 32;
#pragma unroll
    for (int i = 0; i < 32; i += 8)
        tile[threadIdx.y + i][threadIdx.x] =
            in[(r0 + threadIdx.y + i) * ldi + c0 + threadIdx.x];
    __syncthreads();
#pragma unroll
    for (int i = 0; i < 32; i += 8)
        out[(c0 + threadIdx.y + i) * ldo + r0 + threadIdx.x] =
            tile[threadIdx.x][threadIdx.y + i];
}

// W1 transpose with a/g interleave
__global__ void __launch_bounds__(256)
transpose_w1_kernel(const float* __restrict__ in, float* __restrict__ out)
{
    __shared__ float tile[32][33];
    const int z = blockIdx.z;
    in  += (long)z * D_MODEL * (2 * FF);
    out += (long)z * (2 * FF) * D_MODEL;
    const long r0 = (long)blockIdx.y * 32;
    const long c0 = (long)blockIdx.x * 32;
#pragma unroll
    for (int i = 0; i < 32; i += 8)
        tile[threadIdx.y + i][threadIdx.x] =
            in[(r0 + threadIdx.y + i) * (2 * FF) + c0 + threadIdx.x];
    __syncthreads();
#pragma unroll
    for (int i = 0; i < 32; i += 8) {
        const long n = c0 + threadIdx.y + i;
        const long r_out = (n < FF) ? 2 * n : 2 * (n - FF) + 1;
        out[r_out * D_MODEL + r0 + threadIdx.x] = tile[threadIdx.x][threadIdx.y + i];
    }
}

// ---------------------------------------------------------------------------
__global__ void __launch_bounds__(128)
ln_kernel(const float* __restrict__ x, const float* __restrict__ g,
          const float* __restrict__ b, float* __restrict__ o)
{
    __shared__ float sh[4];
    const long row = blockIdx.x;
    const int  t   = threadIdx.x;
    float4 v = ((const float4*)(x + row * D_MODEL))[t];

    float s = v.x + v.y + v.z + v.w;
#pragma unroll
    for (int off = 16; off; off >>= 1) s += __shfl_xor_sync(~0u, s, off);
    if ((t & 31) == 0) sh[t >> 5] = s;
    __syncthreads();
    const float mu = (sh[0] + sh[1] + sh[2] + sh[3]) * (1.f / D_MODEL);

    const float dx = v.x - mu, dy = v.y - mu, dz = v.z - mu, dw = v.w - mu;
    float s2 = dx * dx + dy * dy + dz * dz + dw * dw;
#pragma unroll
    for (int off = 16; off; off >>= 1) s2 += __shfl_xor_sync(~0u, s2, off);
    __syncthreads();
    if ((t & 31) == 0) sh[t >> 5] = s2;
    __syncthreads();
    const float var = (sh[0] + sh[1] + sh[2] + sh[3]) * (1.f / D_MODEL);
    const float r   = rsqrtf(var + 1e-5f);

    float4 gg = ((const float4*)g)[t];
    float4 bb = ((const float4*)b)[t];
    float4 ov;
    ov.x = dx * r * gg.x + bb.x;
    ov.y = dy * r * gg.y + bb.y;
    ov.z = dz * r * gg.z + bb.z;
    ov.w = dw * r * gg.w + bb.w;
    ((float4*)(o + row * D_MODEL))[t] = ov;
}

// ---------------------------------------------------------------------------
// Tau-only sparsemax: warp-per-row, 15-iter bisection + exact Michelot
// refinement; writes ONE float per row (no sim rewrite).
// ---------------------------------------------------------------------------
__global__ void __launch_bounds__(256)
tau_kernel(const float* __restrict__ sim, float* __restrict__ tau)
{
    const long row  = (long)blockIdx.x * 8 + (threadIdx.x >> 5);
    const int  lane = threadIdx.x & 31;
    const float4* base = (const float4*)(sim + row * (long)SEQ);

    float4 z[8];
#pragma unroll
    for (int j = 0; j < 8; ++j) z[j] = base[j * 32 + lane];

    float m = -1e30f;
#pragma unroll
    for (int j = 0; j < 8; ++j)
        m = fmaxf(m, fmaxf(fmaxf(z[j].x, z[j].y), fmaxf(z[j].z, z[j].w)));
#pragma unroll
    for (int off = 16; off; off >>= 1) m = fmaxf(m, __shfl_xor_sync(~0u, m, off));

    float lo = m - 1.f, hi = m;
#pragma unroll 1
    for (int it = 0; it < 15; ++it) {
        const float tv = 0.5f * (lo + hi);
        float s = 0.f;
#pragma unroll
        for (int j = 0; j < 8; ++j) {
            s += fmaxf(z[j].x - tv, 0.f) + fmaxf(z[j].y - tv, 0.f)
               + fmaxf(z[j].z - tv, 0.f) + fmaxf(z[j].w - tv, 0.f);
        }
#pragma unroll
        for (int off = 16; off; off >>= 1) s += __shfl_xor_sync(~0u, s, off);
        if (s >= 1.f) lo = tv; else hi = tv;
    }
    const float tv = 0.5f * (lo + hi);
    float s = 0.f, k = 0.f;
#pragma unroll
    for (int j = 0; j < 8; ++j) {
        if (z[j].x > tv) { s += z[j].x; k += 1.f; }
        if (z[j].y > tv) { s += z[j].y; k += 1.f; }
        if (z[j].z > tv) { s += z[j].z; k += 1.f; }
        if (z[j].w > tv) { s += z[j].w; k += 1.f; }
    }
#pragma unroll
    for (int off = 16; off; off >>= 1) {
        s += __shfl_xor_sync(~0u, s, off);
        k += __shfl_xor_sync(~0u, k, off);
    }
    if (lane == 0) tau[row] = (s - 1.f) / k;
}

// ---------------------------------------------------------------------------
__global__ void __launch_bounds__(512)
pool1_kernel(const float* __restrict__ x, float* __restrict__ p)
{
    const int b = blockIdx.x, cc = blockIdx.y;
    const int d = threadIdx.x;
    float s = 0.f;
    const float* base = x + ((long)b * SEQ + cc * 128) * D_MODEL + d;
    for (int i = 0; i < 128; ++i) s += base[(long)i * D_MODEL];
    p[(b * 8 + cc) * D_MODEL + d] = s;
}

__global__ void __launch_bounds__(256)
pool2_kernel(const float* __restrict__ p, float* __restrict__ o)
{
    const int i = blockIdx.x * blockDim.x + threadIdx.x;
    const int b = i >> 9, d = i & 511;
    float s = 0.f;
#pragma unroll
    for (int cc = 0; cc < 8; ++cc) s += p[(b * 8 + cc) * D_MODEL + d];
    o[i] = s * (1.f / SEQ);
}

// ---------------------------------------------------------------------------
#define SMEM_BN128 (2 * (128 + 128) * 160)
#define SMEM_BN64  (2 * (128 +  64) * 160)

template<int BN, int MODE, bool BSPLIT>
static void launch_mg(const float* A, long lda, long aO, long aI,
                      const float* B, long ldb, long bO, long bI,
                      float* C, long ldc, long cO, long cI,
                      int M, int N, int K, int batches,
                      const float* bias, const float* resid,
                      const float* pos, const float* tau, float alpha)
{
    dim3 grid(N / BN, M / 128, batches);
    const int smem = (BN == 128) ? SMEM_BN128 : SMEM_BN64;
    mgemm_kernel<BN, MODE, BSPLIT><<<grid, 256, smem>>>(
        A, lda, aO, aI, B, ldb, bO, bI, C, ldc, cO, cI, K,
        bias, resid, pos, tau, alpha);
}

extern "C" void kernel_launch(void* const* d_in, const int* in_sizes, int n_in,
                              void* d_out, int out_size)
{
    const float* x      = (const float*)d_in[0];
    const float* proj_w = (const float*)d_in[1];
    const float* proj_b = (const float*)d_in[2];
    const float* pos    = (const float*)d_in[3];
    const float* ln1_g  = (const float*)d_in[4];
    const float* ln1_b  = (const float*)d_in[5];
    const float* wqkv   = (const float*)d_in[6];
    const float* wout   = (const float*)d_in[7];
    const float* bout   = (const float*)d_in[8];
    const float* ln2_g  = (const float*)d_in[9];
    const float* ln2_b  = (const float*)d_in[10];
    const float* w1     = (const float*)d_in[11];
    const float* b1     = (const float*)d_in[12];
    const float* w2     = (const float*)d_in[13];
    const float* b2     = (const float*)d_in[14];
    float* out = (float*)d_out;

    cudaFuncSetAttribute((const void*)mgemm_kernel<128, M_PLAIN, true>,
                         cudaFuncAttributeMaxDynamicSharedMemorySize, SMEM_BN128);
    cudaFuncSetAttribute((const void*)mgemm_kernel<128, M_PLAIN, false>,
                         cudaFuncAttributeMaxDynamicSharedMemorySize, SMEM_BN128);
    cudaFuncSetAttribute((const void*)mgemm_kernel<128, M_GEGLU, true>,
                         cudaFuncAttributeMaxDynamicSharedMemorySize, SMEM_BN128);
    cudaFuncSetAttribute((const void*)mgemm_kernel<64, M_SPAPP, false>,
                         cudaFuncAttributeMaxDynamicSharedMemorySize, SMEM_BN64);

    float *gx, *gh, *gqkv, *gsim, *gtau, *gao, *gffg, *gpool, *gwt, *gws, *gvt;
    cudaGetSymbolAddress((void**)&gx,    g_x);
    cudaGetSymbolAddress((void**)&gh,    g_h);
    cudaGetSymbolAddress((void**)&gqkv,  g_qkv);
    cudaGetSymbolAddress((void**)&gsim,  g_sim);
    cudaGetSymbolAddress((void**)&gtau,  g_tau);
    cudaGetSymbolAddress((void**)&gao,   g_ao);
    cudaGetSymbolAddress((void**)&gffg,  g_ffg);
    cudaGetSymbolAddress((void**)&gpool, g_pool);
    cudaGetSymbolAddress((void**)&gwt,   g_wt);
    cudaGetSymbolAddress((void**)&gws,   g_ws);
    cudaGetSymbolAddress((void**)&gvt,   g_vt);

    // ---- weight transposes (B operands as [N,K] row-major, fp32) ----
    transpose_kernel<<<dim3(16, 16, 1), dim3(32, 8)>>>(
        proj_w, D_MODEL, 0, 0, gwt + OFF_PROJ, D_MODEL, 0, 0);
    transpose_kernel<<<dim3(48, 16, 3), dim3(32, 8)>>>(
        wqkv, 3 * D_MODEL, 0, (long)D_MODEL * 3 * D_MODEL,
        gwt + OFF_QKV, D_MODEL, 0, (long)3 * D_MODEL * D_MODEL);
    transpose_kernel<<<dim3(16, 16, 3), dim3(32, 8)>>>(
        wout, D_MODEL, 0, (long)D_MODEL * D_MODEL,
        gwt + OFF_WOUT, D_MODEL, 0, (long)D_MODEL * D_MODEL);
    transpose_w1_kernel<<<dim3(128, 16, 3), dim3(32, 8)>>>(w1, gwt + OFF_W1);
    transpose_kernel<<<dim3(16, 64, 3), dim3(32, 8)>>>(
        w2, D_MODEL, 0, (long)FF * D_MODEL,
        gwt + OFF_W2, FF, 0, (long)D_MODEL * FF);

    // ---- pre-split all weights into bf16 hi/lo planes ----
    {
        long pairs = (long)512 * 256;
        split_weights_kernel<<<(pairs + 255) / 256, 256>>>(
            gwt + OFF_PROJ, (uint32_t*)(gws + OFF_PROJ), 512, pairs);
        pairs = (long)3 * 1536 * 256;
        split_weights_kernel<<<(pairs + 255) / 256, 256>>>(
            gwt + OFF_QKV, (uint32_t*)(gws + OFF_QKV), 512, pairs);
        pairs = (long)3 * 512 * 256;
        split_weights_kernel<<<(pairs + 255) / 256, 256>>>(
            gwt + OFF_WOUT, (uint32_t*)(gws + OFF_WOUT), 512, pairs);
        pairs = (long)3 * 4096 * 256;
        split_weights_kernel<<<(pairs + 255) / 256, 256>>>(
            gwt + OFF_W1, (uint32_t*)(gws + OFF_W1), 512, pairs);
        pairs = (long)3 * 512 * 1024;
        split_weights_kernel<<<(pairs + 255) / 256, 256>>>(
            gwt + OFF_W2, (uint32_t*)(gws + OFF_W2), 2048, pairs);
    }

    // x = x @ proj_w + proj_b + pos
    launch_mg<128, M_PLAIN, true>(
        x, D_MODEL, 0, 0, gws + OFF_PROJ, D_MODEL, 0, 0,
        gx, D_MODEL, 0, 0, NROWS, D_MODEL, D_MODEL, 1,
        proj_b, nullptr, pos, nullptr, 1.f);

    const float scale = 0.125f;

    for (int l = 0; l < NDEPTH; ++l) {
        ln_kernel<<<NROWS, 128>>>(gx, ln1_g + l * D_MODEL, ln1_b + l * D_MODEL, gh);

        // qkv = h @ Wqkv
        launch_mg<128, M_PLAIN, true>(
            gh, D_MODEL, 0, 0,
            gws + OFF_QKV + (long)l * 3 * D_MODEL * D_MODEL, D_MODEL, 0, 0,
            gqkv, 3 * D_MODEL, 0, 0,
            NROWS, 3 * D_MODEL, D_MODEL, 1, nullptr, nullptr, nullptr, nullptr, 1.f);

        // V^T per (b,h): [1024,64] -> [64,1024]
        transpose_kernel<<<dim3(2, 32, NB * NHEADS), dim3(32, 8)>>>(
            gqkv + 2 * D_MODEL, 3 * D_MODEL, (long)SEQ * 3 * D_MODEL, DHEAD,
            gvt, SEQ, (long)NHEADS * DHEAD * SEQ, (long)DHEAD * SEQ);

        // sim = q @ k^T * scale
        launch_mg<128, M_PLAIN, false>(
            gqkv,           3 * D_MODEL, (long)SEQ * 3 * D_MODEL, DHEAD,
            gqkv + D_MODEL, 3 * D_MODEL, (long)SEQ * 3 * D_MODEL, DHEAD,
            gsim, SEQ, (long)NHEADS * SEQ * SEQ, (long)SEQ * SEQ,
            SEQ, SEQ, DHEAD, NB * NHEADS,
            nullptr, nullptr, nullptr, nullptr, scale);

        // tau per row (no sim rewrite)
        tau_kernel<<<NB * NHEADS * SEQ / 8, 256>>>(gsim, gtau);

        // ao = max(sim - tau, 0) @ v   (sparsemax applied in fragment path)
        launch_mg<64, M_SPAPP, false>(
            gsim, SEQ, (long)NHEADS * SEQ * SEQ, (long)SEQ * SEQ,
            gvt,  SEQ, (long)NHEADS * DHEAD * SEQ, (long)DHEAD * SEQ,
            gao, D_MODEL, (long)SEQ * D_MODEL, DHEAD,
            SEQ, DHEAD, SEQ, NB * NHEADS,
            nullptr, nullptr, nullptr, gtau, 1.f);

        // x = x + ao @ Wout + bout
        launch_mg<128, M_PLAIN, true>(
            gao, D_MODEL, 0, 0,
            gws + OFF_WOUT + (long)l * D_MODEL * D_MODEL, D_MODEL, 0, 0,
            gx, D_MODEL, 0, 0, NROWS, D_MODEL, D_MODEL, 1,
            bout + l * D_MODEL, gx, nullptr, nullptr, 1.f);

        ln_kernel<<<NROWS, 128>>>(gx, ln2_g + l * D_MODEL, ln2_b + l * D_MODEL, gh);

        // ffg = GEGLU(h @ W1 + b1)
        launch_mg<128, M_GEGLU, true>(
            gh, D_MODEL, 0, 0,
            gws + OFF_W1 + (long)l * 2 * FF * D_MODEL, D_MODEL, 0, 0,
            gffg, FF, 0, 0, NROWS, 2 * FF, D_MODEL, 1,
            b1 + (long)l * 2 * FF, nullptr, nullptr, nullptr, 1.f);

        // x = x + ffg @ W2 + b2
        launch_mg<128, M_PLAIN, true>(
            gffg, FF, 0, 0,
            gws + OFF_W2 + (long)l * D_MODEL * FF, FF, 0, 0,
            gx, D_MODEL, 0, 0, NROWS, D_MODEL, FF, 1,
            b2 + l * D_MODEL, gx, nullptr, nullptr, 1.f);
    }

    pool1_kernel<<<dim3(NB, 8), 512>>>(gx, gpool);
    pool2_kernel<<<16, 256>>>(gpool, out);
}

// round 13
// speedup vs baseline: 1.0519x; 1.0157x over previous
#include <cuda_runtime.h>
#include <cmath>
#include <cstdint>

#define D_MODEL 512
#define SEQ     1024
#define NB      8
#define NHEADS  8
#define DHEAD   64
#define FF      2048
#define NROWS   (NB*SEQ)    /* 8192 */
#define NDEPTH  3

// ---------------- scratch (device globals; no allocation allowed) ----------
__device__ float g_x   [NROWS * D_MODEL];
__device__ float g_h   [NROWS * D_MODEL];
__device__ float g_qkv [NROWS * 3 * D_MODEL];
__device__ float g_sim [67108864];                 // 64 * 1024 * 1024
__device__ float g_ao  [NROWS * D_MODEL];
__device__ float g_ffg [NROWS * FF];
__device__ float g_pool[NB * 8 * D_MODEL];
__device__ float g_ws  [12845056];                 // split bf16 hi/lo weight planes
__device__ float g_vt  [NB * NHEADS * DHEAD * SEQ];// V^T split planes per (b,h)

#define OFF_PROJ 0
#define OFF_QKV  262144
#define OFF_WOUT 2621440
#define OFF_W1   3407872
#define OFF_W2   9699328

// GEMM modes
#define M_PLAIN 0
#define M_GEGLU 1

// ---------------------------------------------------------------------------
__device__ __forceinline__ void cp16(uint32_t sa, const float* ga) {
    asm volatile("cp.async.cg.shared.global [%0], [%1], 16;" :: "r"(sa), "l"(ga) : "memory");
}
__device__ __forceinline__ uint32_t smem_u32(const void* p) {
    uint32_t a;
    asm("{ .reg .u64 t; cvta.to.shared.u64 t, %1; cvt.u32.u64 %0, t; }"
        : "=r"(a) : "l"(p));
    return a;
}
__device__ __forceinline__ void cp_commit() {
    asm volatile("cp.async.commit_group;" ::: "memory");
}
// bf16x3 MMA: m16n8k16, row.col, f32 accum
__device__ __forceinline__ void mma16(float* d, const uint32_t* a, const uint32_t* b) {
    asm volatile(
        "mma.sync.aligned.m16n8k16.row.col.f32.bf16.bf16.f32 "
        "{%0,%1,%2,%3}, {%4,%5,%6,%7}, {%8,%9}, {%0,%1,%2,%3};"
        : "+f"(d[0]), "+f"(d[1]), "+f"(d[2]), "+f"(d[3])
        : "r"(a[0]), "r"(a[1]), "r"(a[2]), "r"(a[3]), "r"(b[0]), "r"(b[1]));
}
// split float2 -> packed bf16 hi pair + packed bf16 lo pair
__device__ __forceinline__ void split2(float2 v, uint32_t& hi, uint32_t& lo) {
    asm("cvt.rn.bf16x2.f32 %0, %1, %2;" : "=r"(hi) : "f"(v.y), "f"(v.x));
    const float h0 = __uint_as_float(hi << 16);
    const float h1 = __uint_as_float(hi & 0xFFFF0000u);
    const float r0 = v.x - h0;
    const float r1 = v.y - h1;
    asm("cvt.rn.bf16x2.f32 %0, %1, %2;" : "=r"(lo) : "f"(r1), "f"(r0));
}

// ---------------------------------------------------------------------------
// bf16x3 mma.sync GEMM:  C[M,N] = alpha * A[M,K] @ Bt[N,K]^T (+bias+resid+pos)
// BSPLIT: B is pre-split bf16 (per row, per 32-k chunk = 128B: 16 words of
//   packed (k,k+1) hi pairs, then 16 words of lo pairs). Same bytes/row as
//   fp32 so the stage loader is identical; only the fragment path changes.
// M_GEGLU: B cols interleaved (a0,g0,...); epilogue stores
//   (a+b_a)*gelu(g+b_g) at C[row, col/2], ldc = FF.
// ---------------------------------------------------------------------------
template<int BN, int MODE, bool BSPLIT>
__global__ void __launch_bounds__(256, 2)
mgemm_kernel(const float* __restrict__ A, long lda, long aO, long aI,
             const float* __restrict__ B, long ldb, long bO, long bI,
             float* __restrict__ C, long ldc, long cO, long cI,
             int K,
             const float* __restrict__ bias,
             const float* __restrict__ resid,
             const float* __restrict__ pos,
             float alpha)
{
    constexpr int BM = 128;
    constexpr int WN = BN / 2;       // warp tile: 32 x WN (4x2 warp grid)
    constexpr int NI = WN / 8;       // n-tiles per warp
    constexpr int PITCH = 40;        // floats per smem row (160B)
    constexpr int STAGE_F = (BM + BN) * PITCH;

    extern __shared__ float smem[];

    const int z = blockIdx.z, zo = z >> 3, zi = z & 7;
    A += zo * aO + zi * aI;
    B += zo * bO + zi * bI;
    C += zo * cO + zi * cI;
    const float* Rz = resid ? resid + zo * cO + zi * cI : nullptr;

    const long m0 = (long)blockIdx.y * BM;
    const long n0 = (long)blockIdx.x * BN;
    A += m0 * lda;
    B += n0 * ldb;

    const int t    = threadIdx.x;
    const int wid  = t >> 5, lane = t & 31;
    const int wr   = wid & 3, wc = wid >> 2;
    const int g    = lane >> 2, c = lane & 3;

    const uint32_t sbase = smem_u32(smem);
    const int niter = K >> 5;        // chunks of K=32

    auto load_stage = [&](int s, int kc) {
        const uint32_t sA = sbase + (uint32_t)(s * STAGE_F) * 4u;
        const uint32_t sB = sA + BM * PITCH * 4u;
        const float* ga = A + kc * 32;
        const float* gb = B + kc * 32;
        const int r0  = t >> 3;
        const int seg = (t & 7) * 16;
#pragma unroll
        for (int p = 0; p < BM / 32; ++p) {
            const int r = p * 32 + r0;
            cp16(sA + r * 160 + seg, ga + (long)r * lda + (t & 7) * 4);
        }
#pragma unroll
        for (int p = 0; p < BN / 32; ++p) {
            const int r = p * 32 + r0;
            cp16(sB + r * 160 + seg, gb + (long)r * ldb + (t & 7) * 4);
        }
        cp_commit();
    };

    float acc[2][NI][4];
#pragma unroll
    for (int mi = 0; mi < 2; ++mi)
#pragma unroll
        for (int ni = 0; ni < NI; ++ni)
#pragma unroll
            for (int j = 0; j < 4; ++j) acc[mi][ni][j] = 0.f;

    load_stage(0, 0);

    for (int i = 0; i < niter; ++i) {
        if (i + 1 < niter) {
            load_stage((i + 1) & 1, i + 1);
            asm volatile("cp.async.wait_group 1;" ::: "memory");
        } else {
            asm volatile("cp.async.wait_group 0;" ::: "memory");
        }
        __syncthreads();

        const float* As = smem + (i & 1) * STAGE_F;
        const float* Bs = As + BM * PITCH;
        const uint32_t* Bu = (const uint32_t*)Bs;

#pragma unroll
        for (int ks = 0; ks < 2; ++ks) {      // two k16 steps per K=32 chunk
            const int kk = ks * 16 + 2 * c;
            uint32_t ah[2][4], al[2][4];
#pragma unroll
            for (int mi = 0; mi < 2; ++mi) {
                const int rb = (wr * 32 + mi * 16 + g) * PITCH + kk;
                split2(*(const float2*)&As[rb],                 ah[mi][0], al[mi][0]);
                split2(*(const float2*)&As[rb + 8 * PITCH],     ah[mi][1], al[mi][1]);
                split2(*(const float2*)&As[rb + 8],             ah[mi][2], al[mi][2]);
                split2(*(const float2*)&As[rb + 8 * PITCH + 8], ah[mi][3], al[mi][3]);
            }
            uint32_t bh[NI][2], bl[NI][2];
#pragma unroll
            for (int ni = 0; ni < NI; ++ni) {
                if (BSPLIT) {
                    const int rb2 = (wc * WN + ni * 8 + g) * PITCH + ks * 8 + c;
                    bh[ni][0] = Bu[rb2];
                    bh[ni][1] = Bu[rb2 + 4];
                    bl[ni][0] = Bu[rb2 + 16];
                    bl[ni][1] = Bu[rb2 + 20];
                } else {
                    const int rb = (wc * WN + ni * 8 + g) * PITCH + kk;
                    split2(*(const float2*)&Bs[rb],     bh[ni][0], bl[ni][0]);
                    split2(*(const float2*)&Bs[rb + 8], bh[ni][1], bl[ni][1]);
                }
            }
#pragma unroll
            for (int mi = 0; mi < 2; ++mi)
#pragma unroll
                for (int ni = 0; ni < NI; ++ni) {
                    mma16(acc[mi][ni], al[mi], bh[ni]);
                    mma16(acc[mi][ni], ah[mi], bl[ni]);
                    mma16(acc[mi][ni], ah[mi], bh[ni]);
                }
        }
        __syncthreads();
    }

    // ---- epilogue ----
#pragma unroll
    for (int mi = 0; mi < 2; ++mi) {
#pragma unroll
        for (int ni = 0; ni < NI; ++ni) {
            const long col = n0 + wc * WN + ni * 8 + 2 * c;
#pragma unroll
            for (int h = 0; h < 2; ++h) {
                const long row = m0 + wr * 32 + mi * 16 + g + h * 8;
                float vx = acc[mi][ni][2 * h];
                float vy = acc[mi][ni][2 * h + 1];
                if (MODE == M_GEGLU) {
                    const long j = col >> 1;
                    const float a  = vx + bias[j];
                    const float gg = vy + bias[j + FF];
                    C[row * ldc + j] = a * gg * normcdff(gg);
                } else {
                    vx *= alpha; vy *= alpha;
                    if (bias) {
                        float2 bv = *(const float2*)&bias[col];
                        vx += bv.x; vy += bv.y;
                    }
                    const long off = row * ldc + col;
                    if (Rz) {
                        float2 rv = *(const float2*)&Rz[off];
                        vx += rv.x; vy += rv.y;
                    }
                    if (pos) {
                        float2 pv = *(const float2*)&pos[(row & (SEQ - 1)) * D_MODEL + col];
                        vx += pv.x; vy += pv.y;
                    }
                    *(float2*)&C[off] = make_float2(vx, vy);
                }
            }
        }
    }
}

// ---------------------------------------------------------------------------
// Fused transpose + bf16-split: in [R, C] row-major (ldi) -> out [C, R] in
// split layout (ldo = R): per out-row, per 32-k chunk, 16 hi words then 16 lo
// words of packed (k, k+1) pairs. Batched via z -> (z>>3, z&7).
// ---------------------------------------------------------------------------
__global__ void __launch_bounds__(256)
tsplit_kernel(const float* __restrict__ in, long ldi, long iO, long iI,
              uint32_t* __restrict__ out, long ldo, long oO, long oI)
{
    __shared__ float tile[32][33];
    const int z = blockIdx.z;
    in  += (z >> 3) * iO + (z & 7) * iI;
    out += (z >> 3) * oO + (z & 7) * oI;
    const long r0 = (long)blockIdx.y * 32;   // input-row / output-k block
    const long c0 = (long)blockIdx.x * 32;   // input-col / output-row block
    const int tx = threadIdx.x, ty = threadIdx.y;
#pragma unroll
    for (int i = 0; i < 32; i += 8)
        tile[ty + i][tx] = in[(r0 + ty + i) * ldi + c0 + tx];
    __syncthreads();
    if (tx < 16) {
#pragma unroll
        for (int i = 0; i < 32; i += 8) {
            const long n = c0 + ty + i;
            float2 v = make_float2(tile[2 * tx][ty + i], tile[2 * tx + 1][ty + i]);
            uint32_t hi, lo;
            split2(v, hi, lo);
            out[n * ldo + r0 + tx]      = hi;
            out[n * ldo + r0 + 16 + tx] = lo;
        }
    }
}

// W1 fused transpose+split with a/g interleave: in = w1[l] as [512, 4096];
// out row for orig col n is (n < FF) ? 2n : 2(n-FF)+1; out [4096, 512] split.
__global__ void __launch_bounds__(256)
tsplit_w1_kernel(const float* __restrict__ in, uint32_t* __restrict__ out)
{
    __shared__ float tile[32][33];
    const int z = blockIdx.z;                   // layer
    in  += (long)z * D_MODEL * (2 * FF);
    out += (long)z * (2 * FF) * D_MODEL;
    const long r0 = (long)blockIdx.y * 32;      // k block (0..511)
    const long c0 = (long)blockIdx.x * 32;      // n block (0..4095)
    const int tx = threadIdx.x, ty = threadIdx.y;
#pragma unroll
    for (int i = 0; i < 32; i += 8)
        tile[ty + i][tx] = in[(r0 + ty + i) * (2 * FF) + c0 + tx];
    __syncthreads();
    if (tx < 16) {
#pragma unroll
        for (int i = 0; i < 32; i += 8) {
            const long n = c0 + ty + i;
            const long r_out = (n < FF) ? 2 * n : 2 * (n - FF) + 1;
            float2 v = make_float2(tile[2 * tx][ty + i], tile[2 * tx + 1][ty + i]);
            uint32_t hi, lo;
            split2(v, hi, lo);
            out[r_out * D_MODEL + r0 + tx]      = hi;
            out[r_out * D_MODEL + r0 + 16 + tx] = lo;
        }
    }
}

// ---------------------------------------------------------------------------
__global__ void __launch_bounds__(128)
ln_kernel(const float* __restrict__ x, const float* __restrict__ g,
          const float* __restrict__ b, float* __restrict__ o)
{
    __shared__ float sh[4];
    const long row = blockIdx.x;
    const int  t   = threadIdx.x;
    float4 v = ((const float4*)(x + row * D_MODEL))[t];

    float s = v.x + v.y + v.z + v.w;
#pragma unroll
    for (int off = 16; off; off >>= 1) s += __shfl_xor_sync(~0u, s, off);
    if ((t & 31) == 0) sh[t >> 5] = s;
    __syncthreads();
    const float mu = (sh[0] + sh[1] + sh[2] + sh[3]) * (1.f / D_MODEL);

    const float dx = v.x - mu, dy = v.y - mu, dz = v.z - mu, dw = v.w - mu;
    float s2 = dx * dx + dy * dy + dz * dz + dw * dw;
#pragma unroll
    for (int off = 16; off; off >>= 1) s2 += __shfl_xor_sync(~0u, s2, off);
    __syncthreads();
    if ((t & 31) == 0) sh[t >> 5] = s2;
    __syncthreads();
    const float var = (sh[0] + sh[1] + sh[2] + sh[3]) * (1.f / D_MODEL);
    const float r   = rsqrtf(var + 1e-5f);

    float4 gg = ((const float4*)g)[t];
    float4 bb = ((const float4*)b)[t];
    float4 ov;
    ov.x = dx * r * gg.x + bb.x;
    ov.y = dy * r * gg.y + bb.y;
    ov.z = dz * r * gg.z + bb.z;
    ov.w = dw * r * gg.w + bb.w;
    ((float4*)(o + row * D_MODEL))[t] = ov;
}

// ---------------------------------------------------------------------------
// Sparsemax, warp-per-row: 15-iter bisection + one exact Michelot refinement.
// In place, plain fp32 output.
// ---------------------------------------------------------------------------
__global__ void __launch_bounds__(256)
sparsemax_kernel(float* __restrict__ sim)
{
    const long row  = (long)blockIdx.x * 8 + (threadIdx.x >> 5);
    const int  lane = threadIdx.x & 31;
    float4* base = (float4*)(sim + row * (long)SEQ);

    float4 z[8];
#pragma unroll
    for (int j = 0; j < 8; ++j) z[j] = base[j * 32 + lane];

    float m = -1e30f;
#pragma unroll
    for (int j = 0; j < 8; ++j)
        m = fmaxf(m, fmaxf(fmaxf(z[j].x, z[j].y), fmaxf(z[j].z, z[j].w)));
#pragma unroll
    for (int off = 16; off; off >>= 1) m = fmaxf(m, __shfl_xor_sync(~0u, m, off));

    float lo = m - 1.f, hi = m;
#pragma unroll 1
    for (int it = 0; it < 15; ++it) {
        const float tau = 0.5f * (lo + hi);
        float s = 0.f;
#pragma unroll
        for (int j = 0; j < 8; ++j) {
            s += fmaxf(z[j].x - tau, 0.f) + fmaxf(z[j].y - tau, 0.f)
               + fmaxf(z[j].z - tau, 0.f) + fmaxf(z[j].w - tau, 0.f);
        }
#pragma unroll
        for (int off = 16; off; off >>= 1) s += __shfl_xor_sync(~0u, s, off);
        if (s >= 1.f) lo = tau; else hi = tau;
    }
    // exact refinement on the pinned active set
    {
        const float tau = 0.5f * (lo + hi);
        float s = 0.f, k = 0.f;
#pragma unroll
        for (int j = 0; j < 8; ++j) {
            if (z[j].x > tau) { s += z[j].x; k += 1.f; }
            if (z[j].y > tau) { s += z[j].y; k += 1.f; }
            if (z[j].z > tau) { s += z[j].z; k += 1.f; }
            if (z[j].w > tau) { s += z[j].w; k += 1.f; }
        }
#pragma unroll
        for (int off = 16; off; off >>= 1) {
            s += __shfl_xor_sync(~0u, s, off);
            k += __shfl_xor_sync(~0u, k, off);
        }
        const float tau_x = (s - 1.f) / k;
#pragma unroll
        for (int j = 0; j < 8; ++j) {
            float4 o;
            o.x = fmaxf(z[j].x - tau_x, 0.f);
            o.y = fmaxf(z[j].y - tau_x, 0.f);
            o.z = fmaxf(z[j].z - tau_x, 0.f);
            o.w = fmaxf(z[j].w - tau_x, 0.f);
            base[j * 32 + lane] = o;
        }
    }
}

// ---------------------------------------------------------------------------
__global__ void __launch_bounds__(512)
pool1_kernel(const float* __restrict__ x, float* __restrict__ p)
{
    const int b = blockIdx.x, cc = blockIdx.y;
    const int d = threadIdx.x;
    float s = 0.f;
    const float* base = x + ((long)b * SEQ + cc * 128) * D_MODEL + d;
    for (int i = 0; i < 128; ++i) s += base[(long)i * D_MODEL];
    p[(b * 8 + cc) * D_MODEL + d] = s;
}

__global__ void __launch_bounds__(256)
pool2_kernel(const float* __restrict__ p, float* __restrict__ o)
{
    const int i = blockIdx.x * blockDim.x + threadIdx.x;
    const int b = i >> 9, d = i & 511;
    float s = 0.f;
#pragma unroll
    for (int cc = 0; cc < 8; ++cc) s += p[(b * 8 + cc) * D_MODEL + d];
    o[i] = s * (1.f / SEQ);
}

// ---------------------------------------------------------------------------
#define SMEM_BN128 (2 * (128 + 128) * 160)
#define SMEM_BN64  (2 * (128 +  64) * 160)

template<int BN, int MODE, bool BSPLIT>
static void launch_mg(const float* A, long lda, long aO, long aI,
                      const float* B, long ldb, long bO, long bI,
                      float* C, long ldc, long cO, long cI,
                      int M, int N, int K, int batches,
                      const float* bias, const float* resid,
                      const float* pos, float alpha)
{
    dim3 grid(N / BN, M / 128, batches);
    const int smem = (BN == 128) ? SMEM_BN128 : SMEM_BN64;
    mgemm_kernel<BN, MODE, BSPLIT><<<grid, 256, smem>>>(
        A, lda, aO, aI, B, ldb, bO, bI, C, ldc, cO, cI, K, bias, resid, pos, alpha);
}

extern "C" void kernel_launch(void* const* d_in, const int* in_sizes, int n_in,
                              void* d_out, int out_size)
{
    const float* x      = (const float*)d_in[0];
    const float* proj_w = (const float*)d_in[1];
    const float* proj_b = (const float*)d_in[2];
    const float* pos    = (const float*)d_in[3];
    const float* ln1_g  = (const float*)d_in[4];
    const float* ln1_b  = (const float*)d_in[5];
    const float* wqkv   = (const float*)d_in[6];
    const float* wout   = (const float*)d_in[7];
    const float* bout   = (const float*)d_in[8];
    const float* ln2_g  = (const float*)d_in[9];
    const float* ln2_b  = (const float*)d_in[10];
    const float* w1     = (const float*)d_in[11];
    const float* b1     = (const float*)d_in[12];
    const float* w2     = (const float*)d_in[13];
    const float* b2     = (const float*)d_in[14];
    float* out = (float*)d_out;

    cudaFuncSetAttribute((const void*)mgemm_kernel<128, M_PLAIN, true>,
                         cudaFuncAttributeMaxDynamicSharedMemorySize, SMEM_BN128);
    cudaFuncSetAttribute((const void*)mgemm_kernel<128, M_PLAIN, false>,
                         cudaFuncAttributeMaxDynamicSharedMemorySize, SMEM_BN128);
    cudaFuncSetAttribute((const void*)mgemm_kernel<128, M_GEGLU, true>,
                         cudaFuncAttributeMaxDynamicSharedMemorySize, SMEM_BN128);
    cudaFuncSetAttribute((const void*)mgemm_kernel<64, M_PLAIN, true>,
                         cudaFuncAttributeMaxDynamicSharedMemorySize, SMEM_BN64);

    float *gx, *gh, *gqkv, *gsim, *gao, *gffg, *gpool, *gws, *gvt;
    cudaGetSymbolAddress((void**)&gx,    g_x);
    cudaGetSymbolAddress((void**)&gh,    g_h);
    cudaGetSymbolAddress((void**)&gqkv,  g_qkv);
    cudaGetSymbolAddress((void**)&gsim,  g_sim);
    cudaGetSymbolAddress((void**)&gao,   g_ao);
    cudaGetSymbolAddress((void**)&gffg,  g_ffg);
    cudaGetSymbolAddress((void**)&gpool, g_pool);
    cudaGetSymbolAddress((void**)&gws,   g_ws);
    cudaGetSymbolAddress((void**)&gvt,   g_vt);

    // ---- fused transpose + split weight prep (writes split planes directly) ----
    tsplit_kernel<<<dim3(16, 16, 1), dim3(32, 8)>>>(
        proj_w, D_MODEL, 0, 0,
        (uint32_t*)(gws + OFF_PROJ), D_MODEL, 0, 0);
    tsplit_kernel<<<dim3(48, 16, 3), dim3(32, 8)>>>(
        wqkv, 3 * D_MODEL, 0, (long)D_MODEL * 3 * D_MODEL,
        (uint32_t*)(gws + OFF_QKV), D_MODEL, 0, (long)3 * D_MODEL * D_MODEL);
    tsplit_kernel<<<dim3(16, 16, 3), dim3(32, 8)>>>(
        wout, D_MODEL, 0, (long)D_MODEL * D_MODEL,
        (uint32_t*)(gws + OFF_WOUT), D_MODEL, 0, (long)D_MODEL * D_MODEL);
    tsplit_w1_kernel<<<dim3(128, 16, 3), dim3(32, 8)>>>(w1, (uint32_t*)(gws + OFF_W1));
    tsplit_kernel<<<dim3(16, 64, 3), dim3(32, 8)>>>(
        w2, D_MODEL, 0, (long)FF * D_MODEL,
        (uint32_t*)(gws + OFF_W2), FF, 0, (long)D_MODEL * FF);

    // x = x @ proj_w + proj_b + pos
    launch_mg<128, M_PLAIN, true>(
        x, D_MODEL, 0, 0, gws + OFF_PROJ, D_MODEL, 0, 0,
        gx, D_MODEL, 0, 0, NROWS, D_MODEL, D_MODEL, 1,
        proj_b, nullptr, pos, 1.f);

    const float scale = 0.125f;

    for (int l = 0; l < NDEPTH; ++l) {
        ln_kernel<<<NROWS, 128>>>(gx, ln1_g + l * D_MODEL, ln1_b + l * D_MODEL, gh);

        // qkv = h @ Wqkv
        launch_mg<128, M_PLAIN, true>(
            gh, D_MODEL, 0, 0,
            gws + OFF_QKV + (long)l * 3 * D_MODEL * D_MODEL, D_MODEL, 0, 0,
            gqkv, 3 * D_MODEL, 0, 0,
            NROWS, 3 * D_MODEL, D_MODEL, 1, nullptr, nullptr, nullptr, 1.f);

        // V^T per (b,h): [1024,64] -> [64,1024] in split-bf16 planes
        tsplit_kernel<<<dim3(2, 32, NB * NHEADS), dim3(32, 8)>>>(
            gqkv + 2 * D_MODEL, 3 * D_MODEL, (long)SEQ * 3 * D_MODEL, DHEAD,
            (uint32_t*)gvt, SEQ, (long)NHEADS * DHEAD * SEQ, (long)DHEAD * SEQ);

        // sim = q @ k^T * scale
        launch_mg<128, M_PLAIN, false>(
            gqkv,           3 * D_MODEL, (long)SEQ * 3 * D_MODEL, DHEAD,
            gqkv + D_MODEL, 3 * D_MODEL, (long)SEQ * 3 * D_MODEL, DHEAD,
            gsim, SEQ, (long)NHEADS * SEQ * SEQ, (long)SEQ * SEQ,
            SEQ, SEQ, DHEAD, NB * NHEADS,
            nullptr, nullptr, nullptr, scale);

        sparsemax_kernel<<<NB * NHEADS * SEQ / 8, 256>>>(gsim);

        // ao = attn @ v   (A in-loop split, B = split V^T planes)
        launch_mg<64, M_PLAIN, true>(
            gsim, SEQ, (long)NHEADS * SEQ * SEQ, (long)SEQ * SEQ,
            gvt,  SEQ, (long)NHEADS * DHEAD * SEQ, (long)DHEAD * SEQ,
            gao, D_MODEL, (long)SEQ * D_MODEL, DHEAD,
            SEQ, DHEAD, SEQ, NB * NHEADS,
            nullptr, nullptr, nullptr, 1.f);

        // x = x + ao @ Wout + bout
        launch_mg<128, M_PLAIN, true>(
            gao, D_MODEL, 0, 0,
            gws + OFF_WOUT + (long)l * D_MODEL * D_MODEL, D_MODEL, 0, 0,
            gx, D_MODEL, 0, 0, NROWS, D_MODEL, D_MODEL, 1,
            bout + l * D_MODEL, gx, nullptr, 1.f);

        ln_kernel<<<NROWS, 128>>>(gx, ln2_g + l * D_MODEL, ln2_b + l * D_MODEL, gh);

        // ffg = GEGLU(h @ W1 + b1)   (fused epilogue; W1 interleaved a/g)
        launch_mg<128, M_GEGLU, true>(
            gh, D_MODEL, 0, 0,
            gws + OFF_W1 + (long)l * 2 * FF * D_MODEL, D_MODEL, 0, 0,
            gffg, FF, 0, 0, NROWS, 2 * FF, D_MODEL, 1,
            b1 + (long)l * 2 * FF, nullptr, nullptr, 1.f);

        // x = x + ffg @ W2 + b2
        launch_mg<128, M_PLAIN, true>(
            gffg, FF, 0, 0,
            gws + OFF_W2 + (long)l * D_MODEL * FF, FF, 0, 0,
            gx, D_MODEL, 0, 0, NROWS, D_MODEL, FF, 1,
            b2 + l * D_MODEL, gx, nullptr, 1.f);
    }

    pool1_kernel<<<dim3(NB, 8), 512>>>(gx, gpool);
    pool2_kernel<<<16, 256>>>(gpool, out);
}